// round 5
// baseline (speedup 1.0000x reference)
#include <cuda_runtime.h>
#include <cstdint>

// Problem constants
#define NB 64
#define NN 4096
#define NF 256
#define ND 128
#define NSLOT 8
#define NCHUNK 16

// ---------------- device scratch ----------------
__device__ float g_part[NB*NCHUNK*NSLOT*NF];   // t1 partials [b][c][k][f]
__device__ float g_t2p[NB*NCHUNK*NSLOT];
__device__ float g_t3p[NB*NCHUNK*NSLOT];
__device__ float g_c1[NB*NSLOT*NF];            // lw * q'   [b][k][f]
__device__ float g_c2[NB*NSLOT];
__device__ float g_c3[NB*NSLOT];

__global__ void dummy_k(){}

// =====================================================================
// attn_scan v2: two shuffle-free phases.
// Phase 1: thread-per-row -> stats, logits, softmax -> a, a*rs, mu in smem
// Phase 2: thread-per-(f4,kpair) coalesced accumulate of t1 = sum a*rs*x
// Block = (b, chunk of 256 rows), 256 threads.
// =====================================================================
__global__ void __launch_bounds__(256) attn_scan(const float* __restrict__ X){
  const int b = blockIdx.x, chunk = blockIdx.y;
  const int tid = threadIdx.x;

  __shared__ float s_c1[NSLOT*NF];     // [k][f]
  __shared__ float s_aw[256*NSLOT];    // [r][k] = a*rs
  __shared__ float s_a[256*NSLOT];     // [r][k] = a (raw)
  __shared__ float s_mu[256];
  __shared__ float s_c2[NSLOT], s_c3[NSLOT];

  for (int idx = tid; idx < NSLOT*NF; idx += 256) s_c1[idx] = g_c1[b*NSLOT*NF + idx];
  if (tid < NSLOT){ s_c2[tid] = g_c2[b*NSLOT + tid]; s_c3[tid] = g_c3[b*NSLOT + tid]; }
  __syncthreads();

  // ---------------- phase 1: one row per thread ----------------
  {
    const size_t row = (size_t)b*NN + chunk*256 + tid;
    const float4* xr = (const float4*)(X + row*NF);
    const float4* c1f = (const float4*)s_c1;

    float p[NSLOT];
    #pragma unroll
    for (int k = 0; k < NSLOT; k++) p[k] = 0.f;
    float s = 0.f, q2 = 0.f;

    #pragma unroll 8
    for (int j = 0; j < 64; j++){
      float4 x = __ldg(xr + j);
      s += ((x.x + x.y) + (x.z + x.w));
      q2 = fmaf(x.x, x.x, q2); q2 = fmaf(x.y, x.y, q2);
      q2 = fmaf(x.z, x.z, q2); q2 = fmaf(x.w, x.w, q2);
      #pragma unroll
      for (int k = 0; k < NSLOT; k++){
        float4 c = c1f[k*64 + j];
        float pk = p[k];
        pk = fmaf(x.x, c.x, pk);
        pk = fmaf(x.y, c.y, pk);
        pk = fmaf(x.z, c.z, pk);
        pk = fmaf(x.w, c.w, pk);
        p[k] = pk;
      }
    }
    float mu = s * (1.f/256.f);
    float rs = rsqrtf(fmaf(q2, 1.f/256.f, -mu*mu) + 1e-5f);

    float lg[NSLOT];
    #pragma unroll
    for (int k = 0; k < NSLOT; k++)
      lg[k] = fmaf(rs, fmaf(-mu, s_c2[k], p[k]), s_c3[k]);

    float m = lg[0];
    #pragma unroll
    for (int k = 1; k < NSLOT; k++) m = fmaxf(m, lg[k]);
    float e[NSLOT], es = 0.f;
    #pragma unroll
    for (int k = 0; k < NSLOT; k++){ e[k] = __expf(lg[k] - m); es += e[k]; }
    float inv = __fdividef(1.f, es);

    s_mu[tid] = mu;
    #pragma unroll
    for (int k = 0; k < NSLOT; k++){
      float a = fmaf(e[k], inv, 1e-8f);
      s_a[tid*NSLOT + k]  = a;
      s_aw[tid*NSLOT + k] = a * rs;
    }
  }
  __syncthreads();

  // ---------------- phase 2: coalesced rank-8 accumulate ----------------
  {
    const int f4 = tid & 63;          // float4 column 0..63
    const int kp = tid >> 6;          // k-pair 0..3 -> k0=2kp, k1=2kp+1
    const int k0 = 2*kp, k1 = 2*kp + 1;
    const float4* Xc = (const float4*)(X + (size_t)(b*NN + chunk*256)*NF);

    float4 acc0 = make_float4(0.f,0.f,0.f,0.f);
    float4 acc1 = make_float4(0.f,0.f,0.f,0.f);

    #pragma unroll 4
    for (int r = 0; r < 256; r++){
      float4 x = __ldg(Xc + (size_t)r*64 + f4);
      float a0 = s_aw[r*NSLOT + k0];
      float a1 = s_aw[r*NSLOT + k1];
      acc0.x = fmaf(a0, x.x, acc0.x);
      acc0.y = fmaf(a0, x.y, acc0.y);
      acc0.z = fmaf(a0, x.z, acc0.z);
      acc0.w = fmaf(a0, x.w, acc0.w);
      acc1.x = fmaf(a1, x.x, acc1.x);
      acc1.y = fmaf(a1, x.y, acc1.y);
      acc1.z = fmaf(a1, x.z, acc1.z);
      acc1.w = fmaf(a1, x.w, acc1.w);
    }
    float* gp = g_part + (size_t)(b*NCHUNK + chunk)*NSLOT*NF;
    *(float4*)(gp + k0*NF + f4*4) = acc0;
    *(float4*)(gp + k1*NF + f4*4) = acc1;
  }

  // ---------------- t2/t3 reductions (threads 0..7) ----------------
  if (tid < NSLOT){
    float t2 = 0.f, t3 = 0.f;
    #pragma unroll 4
    for (int r = 0; r < 256; r++){
      t3 += s_a[r*NSLOT + tid];
      t2 = fmaf(s_aw[r*NSLOT + tid], s_mu[r], t2);
    }
    g_t2p[(b*NCHUNK + chunk)*NSLOT + tid] = t2;
    g_t3p[(b*NCHUNK + chunk)*NSLOT + tid] = t3;
  }
}

// =====================================================================
// iter_tail: reduce partials -> weighted -> updates (@Wv) -> GRU -> MLP
//            -> (optionally) next q -> q' -> c1/c2/c3
// =====================================================================
__device__ __forceinline__ float sigm(float x){ return 1.f / (1.f + expf(-x)); }

__global__ void __launch_bounds__(384) iter_tail(float* __restrict__ slots,
    const float* __restrict__ wi, const float* __restrict__ wh,
    const float* __restrict__ bi, const float* __restrict__ bh,
    const float* __restrict__ lnw, const float* __restrict__ lnb,   // ln_mlp
    const float* __restrict__ w1, const float* __restrict__ b1,
    const float* __restrict__ w2, const float* __restrict__ b2,
    const float* __restrict__ Wq, const float* __restrict__ Wk,
    const float* __restrict__ Wv,
    const float* __restrict__ lnqw, const float* __restrict__ lnqb, // ln_slots
    const float* __restrict__ liw, const float* __restrict__ lib,   // ln_in
    int do_q){
  const int b = blockIdx.x, t = threadIdx.x;
  __shared__ float s_wt[2048];
  __shared__ float sbuf[8192];
  float* s_sp  = sbuf;
  float* s_upd = sbuf + 1024;
  float* s_gx  = sbuf + 2048;
  float* s_gh  = sbuf + 5120;
  __shared__ float smu[NSLOT], srs[NSLOT], st2[NSLOT], st3[NSLOT];

  if (t < NSLOT){
    float a2 = 0.f, a3 = 0.f;
    #pragma unroll
    for (int c = 0; c < NCHUNK; c++){
      a2 += g_t2p[(b*NCHUNK + c)*NSLOT + t];
      a3 += g_t3p[(b*NCHUNK + c)*NSLOT + t];
    }
    st2[t] = a2; st3[t] = a3;
  }
  for (int idx = t; idx < 1024; idx += 384) s_sp[idx] = slots[b*1024 + idx];
  __syncthreads();

  for (int idx = t; idx < 2048; idx += 384){
    int k = idx >> 8, f = idx & 255;
    float t1 = 0.f;
    #pragma unroll
    for (int c = 0; c < NCHUNK; c++)
      t1 += g_part[(size_t)(b*NCHUNK + c)*2048 + idx];
    s_wt[idx] = liw[f]*(t1 - st2[k]) + lib[f]*st3[k];
  }
  __syncthreads();

  for (int idx = t; idx < 1024; idx += 384){
    int k = idx >> 7, d = idx & 127;
    float u = 0.f;
    const float* wrow = s_wt + k*256;
    #pragma unroll 4
    for (int f = 0; f < 256; f++) u = fmaf(wrow[f], Wv[f*128 + d], u);
    s_upd[idx] = u / st3[k];
  }
  __syncthreads();

  {
    float ax[NSLOT], ah[NSLOT];
    float bix = bi[t], bhx = bh[t];
    #pragma unroll
    for (int j = 0; j < NSLOT; j++){ ax[j] = bix; ah[j] = bhx; }
    #pragma unroll 2
    for (int d = 0; d < ND; d++){
      float wiv = wi[d*384 + t], whv = wh[d*384 + t];
      #pragma unroll
      for (int j = 0; j < NSLOT; j++){
        ax[j] = fmaf(s_upd[j*ND + d], wiv, ax[j]);
        ah[j] = fmaf(s_sp[j*ND + d],  whv, ah[j]);
      }
    }
    #pragma unroll
    for (int j = 0; j < NSLOT; j++){ s_gx[j*384 + t] = ax[j]; s_gh[j*384 + t] = ah[j]; }
  }
  __syncthreads();

  float* s_mid = s_upd;
  for (int idx = t; idx < 1024; idx += 384){
    int j = idx >> 7, d = idx & 127;
    float r = sigm(s_gx[j*384 + d]        + s_gh[j*384 + d]);
    float z = sigm(s_gx[j*384 + 128 + d]  + s_gh[j*384 + 128 + d]);
    float n = tanhf(fmaf(r, s_gh[j*384 + 256 + d], s_gx[j*384 + 256 + d]));
    s_mid[idx] = (1.f - z) * n + z * s_sp[idx];
  }
  __syncthreads();

  if (t < NSLOT){
    float su = 0.f, sq = 0.f;
    for (int d = 0; d < ND; d++){ float x = s_mid[t*ND + d]; su += x; sq = fmaf(x,x,sq); }
    float mu = su * (1.f/ND);
    smu[t] = mu; srs[t] = rsqrtf(sq*(1.f/ND) - mu*mu + 1e-5f);
  }
  __syncthreads();
  float* s_ln = s_gx;
  float* s_h  = s_gx + 1024;
  for (int idx = t; idx < 1024; idx += 384){
    int j = idx >> 7, d = idx & 127;
    s_ln[idx] = (s_mid[idx] - smu[j]) * srs[j] * lnw[d] + lnb[d];
  }
  __syncthreads();

  for (int idx = t; idx < NSLOT*256; idx += 384){
    int j = idx >> 8, c = idx & 255;
    float h = b1[c];
    #pragma unroll 4
    for (int d = 0; d < ND; d++) h = fmaf(s_ln[j*ND + d], w1[d*256 + c], h);
    s_h[idx] = fmaxf(h, 0.f);
  }
  __syncthreads();

  float* s_new = s_gh;
  for (int idx = t; idx < 1024; idx += 384){
    int j = idx >> 7, d = idx & 127;
    float o = s_mid[idx] + b2[d];
    #pragma unroll 4
    for (int c = 0; c < 256; c++) o = fmaf(s_h[j*256 + c], w2[c*128 + d], o);
    slots[b*1024 + idx] = o;
    s_new[idx] = o;
  }
  __syncthreads();

  if (!do_q) return;

  if (t < NSLOT){
    float su = 0.f, sq = 0.f;
    for (int d = 0; d < ND; d++){ float x = s_new[t*ND + d]; su += x; sq = fmaf(x,x,sq); }
    float mu = su * (1.f/ND);
    smu[t] = mu; srs[t] = rsqrtf(sq*(1.f/ND) - mu*mu + 1e-5f);
  }
  __syncthreads();
  float* s_lnq = s_gh + 1024;
  for (int idx = t; idx < 1024; idx += 384){
    int j = idx >> 7, d = idx & 127;
    s_lnq[idx] = (s_new[idx] - smu[j]) * srs[j] * lnqw[d] + lnqb[d];
  }
  __syncthreads();
  const float inv_scale = 0.08838834764831845f;
  float* s_q = s_wt;
  for (int idx = t; idx < 1024; idx += 384){
    int j = idx >> 7, d = idx & 127;
    float a = 0.f;
    #pragma unroll 4
    for (int f = 0; f < ND; f++) a = fmaf(s_lnq[j*128 + f], Wq[f*128 + d], a);
    s_q[idx] = a * inv_scale;
  }
  __syncthreads();
  float* s_qp = s_gx;
  for (int idx = t; idx < 2048; idx += 384){
    int k = idx >> 8, f = idx & 255;
    float qp = 0.f;
    const float* qrow = s_q + k*128;
    const float* wrow = Wk + f*128;
    #pragma unroll 4
    for (int d = 0; d < ND; d++) qp = fmaf(qrow[d], wrow[d], qp);
    s_qp[idx] = qp;
    g_c1[b*2048 + idx] = liw[f] * qp;
  }
  __syncthreads();
  if (t < NSLOT){
    float a2 = 0.f, a3 = 0.f;
    for (int f = 0; f < 256; f++){
      a2 = fmaf(liw[f], s_qp[t*256 + f], a2);
      a3 = fmaf(lib[f], s_qp[t*256 + f], a3);
    }
    g_c2[b*NSLOT + t] = a2;
    g_c3[b*NSLOT + t] = a3;
  }
}

// =====================================================================
// qprep0: initialize slots in d_out and compute first-iteration c1/c2/c3
// =====================================================================
__global__ void __launch_bounds__(384) qprep0(const float* __restrict__ si,
    float* __restrict__ slots,
    const float* __restrict__ Wq, const float* __restrict__ Wk,
    const float* __restrict__ lnqw, const float* __restrict__ lnqb,
    const float* __restrict__ liw, const float* __restrict__ lib){
  const int b = blockIdx.x, t = threadIdx.x;
  __shared__ float s_new[1024], s_lnq[1024], s_q[1024], s_qp[2048];
  __shared__ float smu[NSLOT], srs[NSLOT];
  for (int idx = t; idx < 1024; idx += 384){
    float v = si[idx];
    s_new[idx] = v;
    slots[b*1024 + idx] = v;
  }
  __syncthreads();
  if (t < NSLOT){
    float su = 0.f, sq = 0.f;
    for (int d = 0; d < ND; d++){ float x = s_new[t*ND + d]; su += x; sq = fmaf(x,x,sq); }
    float mu = su * (1.f/ND);
    smu[t] = mu; srs[t] = rsqrtf(sq*(1.f/ND) - mu*mu + 1e-5f);
  }
  __syncthreads();
  for (int idx = t; idx < 1024; idx += 384){
    int j = idx >> 7, d = idx & 127;
    s_lnq[idx] = (s_new[idx] - smu[j]) * srs[j] * lnqw[d] + lnqb[d];
  }
  __syncthreads();
  const float inv_scale = 0.08838834764831845f;
  for (int idx = t; idx < 1024; idx += 384){
    int j = idx >> 7, d = idx & 127;
    float a = 0.f;
    #pragma unroll 4
    for (int f = 0; f < ND; f++) a = fmaf(s_lnq[j*128 + f], Wq[f*128 + d], a);
    s_q[idx] = a * inv_scale;
  }
  __syncthreads();
  for (int idx = t; idx < 2048; idx += 384){
    int k = idx >> 8, f = idx & 255;
    float qp = 0.f;
    const float* qrow = s_q + k*128;
    const float* wrow = Wk + f*128;
    #pragma unroll 4
    for (int d = 0; d < ND; d++) qp = fmaf(qrow[d], wrow[d], qp);
    s_qp[idx] = qp;
    g_c1[b*2048 + idx] = liw[f] * qp;
  }
  __syncthreads();
  if (t < NSLOT){
    float a2 = 0.f, a3 = 0.f;
    for (int f = 0; f < 256; f++){
      a2 = fmaf(liw[f], s_qp[t*256 + f], a2);
      a3 = fmaf(lib[f], s_qp[t*256 + f], a3);
    }
    g_c2[b*NSLOT + t] = a2;
    g_c3[b*NSLOT + t] = a3;
  }
}

// ---------------- launch ----------------
extern "C" void kernel_launch(void* const* d_in, const int* in_sizes, int n_in,
                              void* d_out, int out_size){
  const float* inputs   = (const float*)d_in[0];
  const float* slotinit = (const float*)d_in[1];
  const float* Wq       = (const float*)d_in[2];
  const float* Wk       = (const float*)d_in[3];
  const float* Wv       = (const float*)d_in[4];
  const float* gru_wi   = (const float*)d_in[5];
  const float* gru_wh   = (const float*)d_in[6];
  const float* gru_bi   = (const float*)d_in[7];
  const float* gru_bh   = (const float*)d_in[8];
  const float* ln_in_w  = (const float*)d_in[9];
  const float* ln_in_b  = (const float*)d_in[10];
  const float* ln_s_w   = (const float*)d_in[11];
  const float* ln_s_b   = (const float*)d_in[12];
  const float* ln_m_w   = (const float*)d_in[13];
  const float* ln_m_b   = (const float*)d_in[14];
  const float* mlp_w1   = (const float*)d_in[15];
  const float* mlp_b1   = (const float*)d_in[16];
  const float* mlp_w2   = (const float*)d_in[17];
  const float* mlp_b2   = (const float*)d_in[18];
  float* out = (float*)d_out;

  qprep0<<<NB, 384>>>(slotinit, out, Wq, Wk, ln_s_w, ln_s_b, ln_in_w, ln_in_b); // 1
  dummy_k<<<1, 32>>>();                                                         // 2
  dummy_k<<<1, 32>>>();                                                         // 3

  for (int it = 0; it < 3; it++){
    attn_scan<<<dim3(NB, NCHUNK), 256>>>(inputs);   // 4th launch on it=0 (ncu)
    iter_tail<<<NB, 384>>>(out, gru_wi, gru_wh, gru_bi, gru_bh,
                           ln_m_w, ln_m_b, mlp_w1, mlp_b1, mlp_w2, mlp_b2,
                           Wq, Wk, Wv, ln_s_w, ln_s_b, ln_in_w, ln_in_b,
                           (it < 2) ? 1 : 0);
  }
}

// round 6
// speedup vs baseline: 1.4333x; 1.4333x over previous
#include <cuda_runtime.h>
#include <cstdint>

// Problem constants
#define NB 64
#define NN 4096
#define NF 256
#define ND 128
#define NSLOT 8
#define RPB 64                 // rows per attn block
#define NCH2 (NN/RPB)          // 64 chunks
#define TSTRIDE 260            // padded tile stride (floats)

// ---------------- device scratch ----------------
__device__ float g_part[(size_t)NB*NCH2*NSLOT*NF];  // [b][c][k][f]  (32MB)
__device__ float g_t2p[NB*NCH2*NSLOT];
__device__ float g_t3p[NB*NCH2*NSLOT];
__device__ float g_c1[NB*NSLOT*NF];                 // lw * q'   [b][k][f]
__device__ float g_c2[NB*NSLOT];
__device__ float g_c3[NB*NSLOT];

__global__ void dummy_k(){}

__device__ __forceinline__ float sigm(float x){ return 1.f / (1.f + expf(-x)); }

#define CPA16(smaddr, gptr) asm volatile("cp.async.cg.shared.global [%0], [%1], 16;\n" :: "r"(smaddr), "l"(gptr))

// =====================================================================
// attn_scan v3: smem-tiled, X read once.
//  - tile: 64 rows x 256 f staged via cp.async (coalesced)
//  - phase 1: 4 threads/row, quarter dots + 2-level shuffle, softmax
//  - phase 2: thread (f4, kpair) accumulates from smem (contig LDS.128)
// Grid (NB, NCH2), 256 threads.
// =====================================================================
__global__ void __launch_bounds__(256) attn_scan(const float* __restrict__ X){
  const int b = blockIdx.x, chunk = blockIdx.y;
  const int tid = threadIdx.x;

  extern __shared__ __align__(16) float tile[];   // [RPB][TSTRIDE]
  __shared__ __align__(16) float s_c1[NSLOT*NF];
  __shared__ float s_a[RPB*NSLOT], s_aw[RPB*NSLOT], s_mu[RPB];
  __shared__ float s_c2[NSLOT], s_c3[NSLOT];
  __shared__ float s_rA[64], s_rB[64];

  // stage tile (coalesced cp.async) + c1/c2/c3
  {
    const float* Xb = X + ((size_t)b*NN + (size_t)chunk*RPB)*NF;
    #pragma unroll
    for (int i = 0; i < 16; i++){
      int idx = tid + i*256;
      int r = idx >> 6, f4 = idx & 63;
      uint32_t dst = (uint32_t)__cvta_generic_to_shared(tile + r*TSTRIDE + f4*4);
      CPA16(dst, Xb + (size_t)r*NF + f4*4);
    }
    asm volatile("cp.async.commit_group;\n" ::);
  }
  for (int i = tid; i < NSLOT*NF; i += 256) s_c1[i] = g_c1[b*NSLOT*NF + i];
  if (tid < NSLOT){ s_c2[tid] = g_c2[b*NSLOT + tid]; s_c3[tid] = g_c3[b*NSLOT + tid]; }
  asm volatile("cp.async.wait_group 0;\n" ::);
  __syncthreads();

  // ---------------- phase 1: 4 threads per row ----------------
  {
    const int r = tid >> 2, q = tid & 3;
    const float4* xr  = (const float4*)(tile + r*TSTRIDE);
    const float4* c1f = (const float4*)s_c1;

    float p[NSLOT];
    #pragma unroll
    for (int k = 0; k < NSLOT; k++) p[k] = 0.f;
    float s = 0.f, q2 = 0.f;

    #pragma unroll
    for (int j = 0; j < 16; j++){
      float4 x = xr[q*16 + j];
      s += ((x.x + x.y) + (x.z + x.w));
      q2 = fmaf(x.x, x.x, q2); q2 = fmaf(x.y, x.y, q2);
      q2 = fmaf(x.z, x.z, q2); q2 = fmaf(x.w, x.w, q2);
      #pragma unroll
      for (int k = 0; k < NSLOT; k++){
        float4 c = c1f[k*64 + q*16 + j];
        float pk = p[k];
        pk = fmaf(x.x, c.x, pk);
        pk = fmaf(x.y, c.y, pk);
        pk = fmaf(x.z, c.z, pk);
        pk = fmaf(x.w, c.w, pk);
        p[k] = pk;
      }
    }
    // combine 4 quarter-threads (lanes differ in bits 0..1)
    #pragma unroll
    for (int off = 1; off <= 2; off <<= 1){
      s  += __shfl_xor_sync(0xffffffffu, s,  off);
      q2 += __shfl_xor_sync(0xffffffffu, q2, off);
      #pragma unroll
      for (int k = 0; k < NSLOT; k++)
        p[k] += __shfl_xor_sync(0xffffffffu, p[k], off);
    }
    float mu = s * (1.f/256.f);
    float rs = rsqrtf(fmaf(q2, 1.f/256.f, -mu*mu) + 1e-5f);

    if (q == 0){
      float lg[NSLOT];
      #pragma unroll
      for (int k = 0; k < NSLOT; k++)
        lg[k] = fmaf(rs, fmaf(-mu, s_c2[k], p[k]), s_c3[k]);
      float m = lg[0];
      #pragma unroll
      for (int k = 1; k < NSLOT; k++) m = fmaxf(m, lg[k]);
      float e[NSLOT], es = 0.f;
      #pragma unroll
      for (int k = 0; k < NSLOT; k++){ e[k] = __expf(lg[k] - m); es += e[k]; }
      float inv = __fdividef(1.f, es);
      s_mu[r] = mu;
      #pragma unroll
      for (int k = 0; k < NSLOT; k++){
        float a = fmaf(e[k], inv, 1e-8f);
        s_a[r*NSLOT + k]  = a;
        s_aw[r*NSLOT + k] = a * rs;
      }
    }
  }
  __syncthreads();

  // ---------------- phase 2: rank-8 accumulate from smem ----------------
  {
    const int f4 = tid & 63, kp = tid >> 6;
    const int k0 = 2*kp, k1 = k0 + 1;
    float4 acc0 = make_float4(0.f,0.f,0.f,0.f);
    float4 acc1 = make_float4(0.f,0.f,0.f,0.f);
    #pragma unroll 4
    for (int r = 0; r < RPB; r++){
      float4 x = *(const float4*)(tile + r*TSTRIDE + f4*4);
      float a0 = s_aw[r*NSLOT + k0];
      float a1 = s_aw[r*NSLOT + k1];
      acc0.x = fmaf(a0, x.x, acc0.x);
      acc0.y = fmaf(a0, x.y, acc0.y);
      acc0.z = fmaf(a0, x.z, acc0.z);
      acc0.w = fmaf(a0, x.w, acc0.w);
      acc1.x = fmaf(a1, x.x, acc1.x);
      acc1.y = fmaf(a1, x.y, acc1.y);
      acc1.z = fmaf(a1, x.z, acc1.z);
      acc1.w = fmaf(a1, x.w, acc1.w);
    }
    float* gp = g_part + (size_t)((b*NCH2 + chunk)*NSLOT)*NF;
    *(float4*)(gp + k0*NF + f4*4) = acc0;
    *(float4*)(gp + k1*NF + f4*4) = acc1;
  }

  // t2/t3 chunk reductions
  if (tid < 64){
    int k = tid >> 3, rg = tid & 7;
    float a3 = 0.f, a2 = 0.f;
    #pragma unroll
    for (int i = 0; i < 8; i++){
      int r = rg*8 + i;
      a3 += s_a[r*NSLOT + k];
      a2 = fmaf(s_aw[r*NSLOT + k], s_mu[r], a2);
    }
    s_rA[tid] = a3; s_rB[tid] = a2;
  }
  __syncthreads();
  if (tid < NSLOT){
    float a3 = 0.f, a2 = 0.f;
    #pragma unroll
    for (int i = 0; i < 8; i++){ a3 += s_rA[tid*8 + i]; a2 += s_rB[tid*8 + i]; }
    g_t3p[(b*NCH2 + chunk)*NSLOT + tid] = a3;
    g_t2p[(b*NCH2 + chunk)*NSLOT + tid] = a2;
  }
}

// =====================================================================
// tail_bk: per-(batch,slot) block. reduce -> updates(@Wv) -> GRU -> MLP
//          -> next q -> q' -> c1/c2/c3.  Grid (NB, NSLOT), 256 threads.
// =====================================================================
__global__ void __launch_bounds__(256) tail_bk(float* __restrict__ slots,
    const float* __restrict__ wi, const float* __restrict__ wh,
    const float* __restrict__ bi, const float* __restrict__ bh,
    const float* __restrict__ lnw, const float* __restrict__ lnb,   // ln_mlp
    const float* __restrict__ w1, const float* __restrict__ b1,
    const float* __restrict__ w2, const float* __restrict__ b2,
    const float* __restrict__ Wq, const float* __restrict__ Wk,
    const float* __restrict__ Wv,
    const float* __restrict__ lnqw, const float* __restrict__ lnqb, // ln_slots
    const float* __restrict__ liw, const float* __restrict__ lib,   // ln_in
    int do_q){
  const int b = blockIdx.x, k = blockIdx.y, t = threadIdx.x;
  __shared__ __align__(16) float s_wt[256];
  __shared__ float s_sp[128], s_upd[128], s_gx[384], s_gh[384];
  __shared__ float s_mid[128], s_ln[128], s_h[256], s_new[128];
  __shared__ __align__(16) float s_q[128];
  __shared__ float s_qp[256];
  __shared__ float s_red[256];
  __shared__ float s_sc[8];

  if (t < 128) s_sp[t] = slots[b*1024 + k*128 + t];

  // t2/t3 totals over 64 chunks
  if (t < 64){
    s_red[t]      = g_t2p[(b*NCH2 + t)*NSLOT + k];
    s_red[64 + t] = g_t3p[(b*NCH2 + t)*NSLOT + k];
  }
  __syncthreads();
  if (t == 0){
    float a2 = 0.f, a3 = 0.f;
    #pragma unroll 8
    for (int c = 0; c < 64; c++){ a2 += s_red[c]; a3 += s_red[64 + c]; }
    s_sc[0] = a2; s_sc[1] = a3;
  }
  __syncthreads();
  const float st2 = s_sc[0], st3 = s_sc[1];

  // weighted[f] = liw*(t1 - t2) + lib*t3
  {
    float t1 = 0.f;
    const float* gp = g_part + (size_t)(b*NCH2*NSLOT)*NF + k*NF + t;
    #pragma unroll 8
    for (int c = 0; c < 64; c++) t1 += gp[(size_t)c*NSLOT*NF];
    s_wt[t] = liw[t]*(t1 - st2) + lib[t]*st3;
  }
  __syncthreads();

  // updates[d] = (weighted @ Wv)/t3   (2 threads per d, split f)
  {
    int d = t & 127, h = t >> 7;
    float u = 0.f;
    #pragma unroll 4
    for (int f = h*128; f < h*128 + 128; f++)
      u = fmaf(s_wt[f], __ldg(Wv + f*128 + d), u);
    s_red[t] = u;
  }
  __syncthreads();
  if (t < 128) s_upd[t] = (s_red[t] + s_red[t + 128]) / st3;
  __syncthreads();

  // GRU gates
  for (int g = t; g < 384; g += 256){
    float ax = bi[g], ah = bh[g];
    #pragma unroll 4
    for (int d = 0; d < 128; d++){
      ax = fmaf(s_upd[d], __ldg(wi + d*384 + g), ax);
      ah = fmaf(s_sp[d],  __ldg(wh + d*384 + g), ah);
    }
    s_gx[g] = ax; s_gh[g] = ah;
  }
  __syncthreads();

  if (t < 128){
    float r = sigm(s_gx[t] + s_gh[t]);
    float z = sigm(s_gx[128 + t] + s_gh[128 + t]);
    float n = tanhf(fmaf(r, s_gh[256 + t], s_gx[256 + t]));
    s_mid[t] = (1.f - z)*n + z*s_sp[t];
  }
  __syncthreads();

  // LN(mid) stats
  if (t < 128){
    float x = s_mid[t], xs = x, xq = x*x;
    #pragma unroll
    for (int off = 16; off; off >>= 1){
      xs += __shfl_xor_sync(0xffffffffu, xs, off);
      xq += __shfl_xor_sync(0xffffffffu, xq, off);
    }
    if ((t & 31) == 0){ s_red[t >> 5] = xs; s_red[8 + (t >> 5)] = xq; }
  }
  __syncthreads();
  if (t == 0){
    float su = 0.f, sq = 0.f;
    #pragma unroll
    for (int i = 0; i < 4; i++){ su += s_red[i]; sq += s_red[8 + i]; }
    float mu = su * (1.f/128.f);
    s_sc[2] = mu; s_sc[3] = rsqrtf(sq*(1.f/128.f) - mu*mu + 1e-5f);
  }
  __syncthreads();
  if (t < 128) s_ln[t] = (s_mid[t] - s_sc[2])*s_sc[3]*lnw[t] + lnb[t];
  __syncthreads();

  // hidden[c] = relu(ln @ w1 + b1)
  {
    float h = b1[t];
    #pragma unroll 4
    for (int d = 0; d < 128; d++) h = fmaf(s_ln[d], __ldg(w1 + d*256 + t), h);
    s_h[t] = fmaxf(h, 0.f);
  }
  __syncthreads();

  // out[d] = mid + hidden @ w2 + b2   (2 threads per d)
  {
    int d = t & 127, hh = t >> 7;
    float o = 0.f;
    #pragma unroll 4
    for (int c = hh*128; c < hh*128 + 128; c++)
      o = fmaf(s_h[c], __ldg(w2 + c*128 + d), o);
    s_red[t] = o;
  }
  __syncthreads();
  if (t < 128){
    float o = s_mid[t] + b2[t] + s_red[t] + s_red[t + 128];
    slots[b*1024 + k*128 + t] = o;
    s_new[t] = o;
  }
  if (!do_q) return;
  __syncthreads();

  // LN(new) with ln_slots
  if (t < 128){
    float x = s_new[t], xs = x, xq = x*x;
    #pragma unroll
    for (int off = 16; off; off >>= 1){
      xs += __shfl_xor_sync(0xffffffffu, xs, off);
      xq += __shfl_xor_sync(0xffffffffu, xq, off);
    }
    if ((t & 31) == 0){ s_red[t >> 5] = xs; s_red[8 + (t >> 5)] = xq; }
  }
  __syncthreads();
  if (t == 0){
    float su = 0.f, sq = 0.f;
    #pragma unroll
    for (int i = 0; i < 4; i++){ su += s_red[i]; sq += s_red[8 + i]; }
    float mu = su * (1.f/128.f);
    s_sc[4] = mu; s_sc[5] = rsqrtf(sq*(1.f/128.f) - mu*mu + 1e-5f);
  }
  __syncthreads();
  if (t < 128) s_ln[t] = (s_new[t] - s_sc[4])*s_sc[5]*lnqw[t] + lnqb[t];
  __syncthreads();

  // q[d] = (lnq @ Wq) * 1/sqrt(D)
  if (t < 128){
    float a = 0.f;
    #pragma unroll 4
    for (int f = 0; f < 128; f++) a = fmaf(s_ln[f], __ldg(Wq + f*128 + t), a);
    s_q[t] = a * 0.08838834764831845f;
  }
  __syncthreads();

  // q'[f] = Wk[f,:] . q  (warp-per-row GEMV, coalesced float4)
  {
    int w = t >> 5, lane = t & 31;
    float4 qv = ((const float4*)s_q)[lane];
    for (int i = 0; i < 32; i++){
      int f = w*32 + i;
      float4 wk = __ldg((const float4*)(Wk + f*128) + lane);
      float pp = wk.x*qv.x;
      pp = fmaf(wk.y, qv.y, pp);
      pp = fmaf(wk.z, qv.z, pp);
      pp = fmaf(wk.w, qv.w, pp);
      #pragma unroll
      for (int off = 16; off; off >>= 1)
        pp += __shfl_xor_sync(0xffffffffu, pp, off);
      if (lane == 0){
        s_qp[f] = pp;
        g_c1[b*(NSLOT*NF) + k*NF + f] = liw[f] * pp;
      }
    }
  }
  __syncthreads();

  // c2/c3
  {
    float a2 = liw[t]*s_qp[t], a3 = lib[t]*s_qp[t];
    #pragma unroll
    for (int off = 16; off; off >>= 1){
      a2 += __shfl_xor_sync(0xffffffffu, a2, off);
      a3 += __shfl_xor_sync(0xffffffffu, a3, off);
    }
    if ((t & 31) == 0){ s_red[t >> 5] = a2; s_red[16 + (t >> 5)] = a3; }
  }
  __syncthreads();
  if (t == 0){
    float a2 = 0.f, a3 = 0.f;
    #pragma unroll
    for (int i = 0; i < 8; i++){ a2 += s_red[i]; a3 += s_red[16 + i]; }
    g_c2[b*NSLOT + k] = a2;
    g_c3[b*NSLOT + k] = a3;
  }
}

// =====================================================================
// qprep0: init slots + first-iteration c1/c2/c3
// =====================================================================
__global__ void __launch_bounds__(384) qprep0(const float* __restrict__ si,
    float* __restrict__ slots,
    const float* __restrict__ Wq, const float* __restrict__ Wk,
    const float* __restrict__ lnqw, const float* __restrict__ lnqb,
    const float* __restrict__ liw, const float* __restrict__ lib){
  const int b = blockIdx.x, t = threadIdx.x;
  __shared__ float s_new[1024], s_lnq[1024], s_q[1024], s_qp[2048];
  __shared__ float smu[NSLOT], srs[NSLOT];
  for (int idx = t; idx < 1024; idx += 384){
    float v = si[idx];
    s_new[idx] = v;
    slots[b*1024 + idx] = v;
  }
  __syncthreads();
  if (t < NSLOT){
    float su = 0.f, sq = 0.f;
    for (int d = 0; d < ND; d++){ float x = s_new[t*ND + d]; su += x; sq = fmaf(x,x,sq); }
    float mu = su * (1.f/ND);
    smu[t] = mu; srs[t] = rsqrtf(sq*(1.f/ND) - mu*mu + 1e-5f);
  }
  __syncthreads();
  for (int idx = t; idx < 1024; idx += 384){
    int j = idx >> 7, d = idx & 127;
    s_lnq[idx] = (s_new[idx] - smu[j]) * srs[j] * lnqw[d] + lnqb[d];
  }
  __syncthreads();
  const float inv_scale = 0.08838834764831845f;
  for (int idx = t; idx < 1024; idx += 384){
    int j = idx >> 7, d = idx & 127;
    float a = 0.f;
    #pragma unroll 4
    for (int f = 0; f < ND; f++) a = fmaf(s_lnq[j*128 + f], Wq[f*128 + d], a);
    s_q[idx] = a * inv_scale;
  }
  __syncthreads();
  for (int idx = t; idx < 2048; idx += 384){
    int k = idx >> 8, f = idx & 255;
    float qp = 0.f;
    const float* qrow = s_q + k*128;
    const float* wrow = Wk + f*128;
    #pragma unroll 4
    for (int d = 0; d < ND; d++) qp = fmaf(qrow[d], wrow[d], qp);
    s_qp[idx] = qp;
    g_c1[b*2048 + idx] = liw[f] * qp;
  }
  __syncthreads();
  if (t < NSLOT){
    float a2 = 0.f, a3 = 0.f;
    for (int f = 0; f < 256; f++){
      a2 = fmaf(liw[f], s_qp[t*256 + f], a2);
      a3 = fmaf(lib[f], s_qp[t*256 + f], a3);
    }
    g_c2[b*NSLOT + t] = a2;
    g_c3[b*NSLOT + t] = a3;
  }
}

// ---------------- launch ----------------
#define ATTN_SMEM (RPB*TSTRIDE*4)

extern "C" void kernel_launch(void* const* d_in, const int* in_sizes, int n_in,
                              void* d_out, int out_size){
  const float* inputs   = (const float*)d_in[0];
  const float* slotinit = (const float*)d_in[1];
  const float* Wq       = (const float*)d_in[2];
  const float* Wk       = (const float*)d_in[3];
  const float* Wv       = (const float*)d_in[4];
  const float* gru_wi   = (const float*)d_in[5];
  const float* gru_wh   = (const float*)d_in[6];
  const float* gru_bi   = (const float*)d_in[7];
  const float* gru_bh   = (const float*)d_in[8];
  const float* ln_in_w  = (const float*)d_in[9];
  const float* ln_in_b  = (const float*)d_in[10];
  const float* ln_s_w   = (const float*)d_in[11];
  const float* ln_s_b   = (const float*)d_in[12];
  const float* ln_m_w   = (const float*)d_in[13];
  const float* ln_m_b   = (const float*)d_in[14];
  const float* mlp_w1   = (const float*)d_in[15];
  const float* mlp_b1   = (const float*)d_in[16];
  const float* mlp_w2   = (const float*)d_in[17];
  const float* mlp_b2   = (const float*)d_in[18];
  float* out = (float*)d_out;

  cudaFuncSetAttribute(attn_scan, cudaFuncAttributeMaxDynamicSharedMemorySize, ATTN_SMEM);

  qprep0<<<NB, 384>>>(slotinit, out, Wq, Wk, ln_s_w, ln_s_b, ln_in_w, ln_in_b); // 1
  dummy_k<<<1, 32>>>();                                                         // 2
  dummy_k<<<1, 32>>>();                                                         // 3

  for (int it = 0; it < 3; it++){
    attn_scan<<<dim3(NB, NCH2), 256, ATTN_SMEM>>>(inputs);   // 4th launch on it=0
    tail_bk<<<dim3(NB, NSLOT), 256>>>(out, gru_wi, gru_wh, gru_bi, gru_bh,
                           ln_m_w, ln_m_b, mlp_w1, mlp_b1, mlp_w2, mlp_b2,
                           Wq, Wk, Wv, ln_s_w, ln_s_b, ln_in_w, ln_in_b,
                           (it < 2) ? 1 : 0);
  }
}

// round 7
// speedup vs baseline: 2.0229x; 1.4114x over previous
#include <cuda_runtime.h>
#include <cstdint>

// Problem constants
#define NB 64
#define NN 4096
#define NF 256
#define ND 128
#define NSLOT 8
#define NCH 128                 // warp-chunks per batch (32 rows each)

// ---------------- device scratch ----------------
__device__ float g_part[(size_t)NB*NCH*NSLOT*NF];   // [b][wc][k][f]  (67MB)
__device__ float g_t2p[NB*NCH*NSLOT];
__device__ float g_t3p[NB*NCH*NSLOT];
__device__ float g_c1[NB*NSLOT*NF];                 // lw * q'   [b][k][f]
__device__ float g_c2[NB*NSLOT];
__device__ float g_c3[NB*NSLOT];

__global__ void dummy_k(){}

__device__ __forceinline__ float sigm(float x){ return 1.f / (1.f + expf(-x)); }

// =====================================================================
// attn_scan v4: register-resident, zero smem.
// Warp owns 32 rows; lane owns f = 4*lane..+3 and 128+4*lane..+3.
// c1 fragments and t1 accumulators live in registers.
// Grid (NB, 32), 128 threads (4 warps); wc = blockIdx.y*4 + warp.
// =====================================================================
__global__ void __launch_bounds__(128, 2) attn_scan(const float* __restrict__ X){
  const int b = blockIdx.x;
  const int warp = threadIdx.x >> 5, lane = threadIdx.x & 31;
  const int wc = blockIdx.y * 4 + warp;

  // c1 fragments (64 regs), c2/c3 (redundant uniform)
  float4 c1a[NSLOT], c1b[NSLOT];
  float c2[NSLOT], c3[NSLOT];
  {
    const float* c1p = g_c1 + b*NSLOT*NF;
    #pragma unroll
    for (int k = 0; k < NSLOT; k++){
      c1a[k] = __ldg((const float4*)(c1p + k*NF) + lane);
      c1b[k] = __ldg((const float4*)(c1p + k*NF + 128) + lane);
      c2[k] = __ldg(g_c2 + b*NSLOT + k);
      c3[k] = __ldg(g_c3 + b*NSLOT + k);
    }
  }

  // t1 accumulators (64 regs) + t2/t3 (redundant across lanes)
  float4 A0[NSLOT], A1[NSLOT];
  float t2a[NSLOT], t3a[NSLOT];
  #pragma unroll
  for (int k = 0; k < NSLOT; k++){
    A0[k] = make_float4(0.f,0.f,0.f,0.f);
    A1[k] = make_float4(0.f,0.f,0.f,0.f);
    t2a[k] = 0.f; t3a[k] = 0.f;
  }

  const float* Xb = X + ((size_t)b*NN + (size_t)wc*32)*NF;
  for (int r = 0; r < 32; r++){
    const float4* xr = (const float4*)(Xb + (size_t)r*NF);
    float4 x0 = __ldg(xr + lane);
    float4 x1 = __ldg(xr + 32 + lane);

    // stats partials
    float s  = ((x0.x + x0.y) + (x0.z + x0.w)) + ((x1.x + x1.y) + (x1.z + x1.w));
    float q2 = x0.x*x0.x;
    q2 = fmaf(x0.y, x0.y, q2); q2 = fmaf(x0.z, x0.z, q2); q2 = fmaf(x0.w, x0.w, q2);
    q2 = fmaf(x1.x, x1.x, q2); q2 = fmaf(x1.y, x1.y, q2);
    q2 = fmaf(x1.z, x1.z, q2); q2 = fmaf(x1.w, x1.w, q2);

    // dot partials (c1 from registers)
    float p[NSLOT];
    #pragma unroll
    for (int k = 0; k < NSLOT; k++){
      float pk = x0.x*c1a[k].x;
      pk = fmaf(x0.y, c1a[k].y, pk);
      pk = fmaf(x0.z, c1a[k].z, pk);
      pk = fmaf(x0.w, c1a[k].w, pk);
      pk = fmaf(x1.x, c1b[k].x, pk);
      pk = fmaf(x1.y, c1b[k].y, pk);
      pk = fmaf(x1.z, c1b[k].z, pk);
      pk = fmaf(x1.w, c1b[k].w, pk);
      p[k] = pk;
    }

    // 10-value XOR butterfly: every lane ends with full sums
    #pragma unroll
    for (int off = 16; off; off >>= 1){
      s  += __shfl_xor_sync(0xffffffffu, s,  off);
      q2 += __shfl_xor_sync(0xffffffffu, q2, off);
      #pragma unroll
      for (int k = 0; k < NSLOT; k++)
        p[k] += __shfl_xor_sync(0xffffffffu, p[k], off);
    }

    float mu = s * (1.f/256.f);
    float rs = rsqrtf(fmaf(q2, 1.f/256.f, -mu*mu) + 1e-5f);

    // softmax over 8 slots (redundant in all lanes)
    float lg[NSLOT];
    #pragma unroll
    for (int k = 0; k < NSLOT; k++)
      lg[k] = fmaf(rs, fmaf(-mu, c2[k], p[k]), c3[k]);
    float m = fmaxf(fmaxf(fmaxf(lg[0],lg[1]), fmaxf(lg[2],lg[3])),
                    fmaxf(fmaxf(lg[4],lg[5]), fmaxf(lg[6],lg[7])));
    float e[NSLOT], es = 0.f;
    #pragma unroll
    for (int k = 0; k < NSLOT; k++){ e[k] = __expf(lg[k] - m); es += e[k]; }
    float inv = __fdividef(1.f, es);

    #pragma unroll
    for (int k = 0; k < NSLOT; k++){
      float a  = fmaf(e[k], inv, 1e-8f);
      float ar = a * rs;
      t3a[k] += a;
      t2a[k] = fmaf(ar, mu, t2a[k]);
      A0[k].x = fmaf(ar, x0.x, A0[k].x);
      A0[k].y = fmaf(ar, x0.y, A0[k].y);
      A0[k].z = fmaf(ar, x0.z, A0[k].z);
      A0[k].w = fmaf(ar, x0.w, A0[k].w);
      A1[k].x = fmaf(ar, x1.x, A1[k].x);
      A1[k].y = fmaf(ar, x1.y, A1[k].y);
      A1[k].z = fmaf(ar, x1.z, A1[k].z);
      A1[k].w = fmaf(ar, x1.w, A1[k].w);
    }
  }

  // write partials (coalesced)
  float* gp = g_part + (size_t)((b*NCH + wc)*NSLOT)*NF;
  #pragma unroll
  for (int k = 0; k < NSLOT; k++){
    *(float4*)(gp + k*NF + lane*4)       = A0[k];
    *(float4*)(gp + k*NF + 128 + lane*4) = A1[k];
  }
  if (lane == 0){
    #pragma unroll
    for (int k = 0; k < NSLOT; k++){
      g_t2p[(b*NCH + wc)*NSLOT + k] = t2a[k];
      g_t3p[(b*NCH + wc)*NSLOT + k] = t3a[k];
    }
  }
}

// =====================================================================
// tail_bk: per-(batch,slot) block. reduce -> updates(@Wv) -> GRU -> MLP
//          -> next q -> q' -> c1/c2/c3.  Grid (NB, NSLOT), 256 threads.
// =====================================================================
__global__ void __launch_bounds__(256) tail_bk(float* __restrict__ slots,
    const float* __restrict__ wi, const float* __restrict__ wh,
    const float* __restrict__ bi, const float* __restrict__ bh,
    const float* __restrict__ lnw, const float* __restrict__ lnb,   // ln_mlp
    const float* __restrict__ w1, const float* __restrict__ b1,
    const float* __restrict__ w2, const float* __restrict__ b2,
    const float* __restrict__ Wq, const float* __restrict__ Wk,
    const float* __restrict__ Wv,
    const float* __restrict__ lnqw, const float* __restrict__ lnqb, // ln_slots
    const float* __restrict__ liw, const float* __restrict__ lib,   // ln_in
    int do_q){
  const int b = blockIdx.x, k = blockIdx.y, t = threadIdx.x;
  __shared__ __align__(16) float s_wt[256];
  __shared__ float s_sp[128], s_upd[128], s_gx[384], s_gh[384];
  __shared__ float s_mid[128], s_ln[128], s_h[256], s_new[128];
  __shared__ __align__(16) float s_q[128];
  __shared__ float s_qp[256];
  __shared__ float s_red[256];
  __shared__ float s_sc[8];

  if (t < 128) s_sp[t] = slots[b*1024 + k*128 + t];

  // t2/t3 totals over 128 chunks
  if (t < 128) s_red[t] = g_t2p[(b*NCH + t)*NSLOT + k];
  else         s_red[t] = g_t3p[(b*NCH + (t - 128))*NSLOT + k];
  __syncthreads();
  if (t == 0){
    float a2 = 0.f, a3 = 0.f;
    #pragma unroll 8
    for (int c = 0; c < 128; c++){ a2 += s_red[c]; a3 += s_red[128 + c]; }
    s_sc[0] = a2; s_sc[1] = a3;
  }
  __syncthreads();
  const float st2 = s_sc[0], st3 = s_sc[1];

  // weighted[f] = liw*(t1 - t2) + lib*t3
  {
    float t1 = 0.f;
    const float* gp = g_part + (size_t)(b*NCH*NSLOT)*NF + k*NF + t;
    #pragma unroll 8
    for (int c = 0; c < NCH; c++) t1 += gp[(size_t)c*NSLOT*NF];
    s_wt[t] = liw[t]*(t1 - st2) + lib[t]*st3;
  }
  __syncthreads();

  // updates[d] = (weighted @ Wv)/t3   (2 threads per d, split f)
  {
    int d = t & 127, h = t >> 7;
    float u = 0.f;
    #pragma unroll 8
    for (int f = h*128; f < h*128 + 128; f++)
      u = fmaf(s_wt[f], __ldg(Wv + f*128 + d), u);
    s_red[t] = u;
  }
  __syncthreads();
  if (t < 128) s_upd[t] = (s_red[t] + s_red[t + 128]) / st3;
  __syncthreads();

  // GRU gates
  for (int g = t; g < 384; g += 256){
    float ax = bi[g], ah = bh[g];
    #pragma unroll 8
    for (int d = 0; d < 128; d++){
      ax = fmaf(s_upd[d], __ldg(wi + d*384 + g), ax);
      ah = fmaf(s_sp[d],  __ldg(wh + d*384 + g), ah);
    }
    s_gx[g] = ax; s_gh[g] = ah;
  }
  __syncthreads();

  if (t < 128){
    float r = sigm(s_gx[t] + s_gh[t]);
    float z = sigm(s_gx[128 + t] + s_gh[128 + t]);
    float n = tanhf(fmaf(r, s_gh[256 + t], s_gx[256 + t]));
    s_mid[t] = (1.f - z)*n + z*s_sp[t];
  }
  __syncthreads();

  // LN(mid) stats
  if (t < 128){
    float x = s_mid[t], xs = x, xq = x*x;
    #pragma unroll
    for (int off = 16; off; off >>= 1){
      xs += __shfl_xor_sync(0xffffffffu, xs, off);
      xq += __shfl_xor_sync(0xffffffffu, xq, off);
    }
    if ((t & 31) == 0){ s_red[t >> 5] = xs; s_red[8 + (t >> 5)] = xq; }
  }
  __syncthreads();
  if (t == 0){
    float su = 0.f, sq = 0.f;
    #pragma unroll
    for (int i = 0; i < 4; i++){ su += s_red[i]; sq += s_red[8 + i]; }
    float mu = su * (1.f/128.f);
    s_sc[2] = mu; s_sc[3] = rsqrtf(sq*(1.f/128.f) - mu*mu + 1e-5f);
  }
  __syncthreads();
  if (t < 128) s_ln[t] = (s_mid[t] - s_sc[2])*s_sc[3]*lnw[t] + lnb[t];
  __syncthreads();

  // hidden[c] = relu(ln @ w1 + b1)
  {
    float h = b1[t];
    #pragma unroll 8
    for (int d = 0; d < 128; d++) h = fmaf(s_ln[d], __ldg(w1 + d*256 + t), h);
    s_h[t] = fmaxf(h, 0.f);
  }
  __syncthreads();

  // out[d] = mid + hidden @ w2 + b2   (2 threads per d)
  {
    int d = t & 127, hh = t >> 7;
    float o = 0.f;
    #pragma unroll 8
    for (int c = hh*128; c < hh*128 + 128; c++)
      o = fmaf(s_h[c], __ldg(w2 + c*128 + d), o);
    s_red[t] = o;
  }
  __syncthreads();
  if (t < 128){
    float o = s_mid[t] + b2[t] + s_red[t] + s_red[t + 128];
    slots[b*1024 + k*128 + t] = o;
    s_new[t] = o;
  }
  if (!do_q) return;
  __syncthreads();

  // LN(new) with ln_slots
  if (t < 128){
    float x = s_new[t], xs = x, xq = x*x;
    #pragma unroll
    for (int off = 16; off; off >>= 1){
      xs += __shfl_xor_sync(0xffffffffu, xs, off);
      xq += __shfl_xor_sync(0xffffffffu, xq, off);
    }
    if ((t & 31) == 0){ s_red[t >> 5] = xs; s_red[8 + (t >> 5)] = xq; }
  }
  __syncthreads();
  if (t == 0){
    float su = 0.f, sq = 0.f;
    #pragma unroll
    for (int i = 0; i < 4; i++){ su += s_red[i]; sq += s_red[8 + i]; }
    float mu = su * (1.f/128.f);
    s_sc[4] = mu; s_sc[5] = rsqrtf(sq*(1.f/128.f) - mu*mu + 1e-5f);
  }
  __syncthreads();
  if (t < 128) s_ln[t] = (s_new[t] - s_sc[4])*s_sc[5]*lnqw[t] + lnqb[t];
  __syncthreads();

  // q[d] = (lnq @ Wq) * 1/sqrt(D)
  if (t < 128){
    float a = 0.f;
    #pragma unroll 8
    for (int f = 0; f < 128; f++) a = fmaf(s_ln[f], __ldg(Wq + f*128 + t), a);
    s_q[t] = a * 0.08838834764831845f;
  }
  __syncthreads();

  // q'[f] = Wk[f,:] . q  (warp-per-row GEMV, coalesced float4)
  {
    int w = t >> 5, lane = t & 31;
    float4 qv = ((const float4*)s_q)[lane];
    for (int i = 0; i < 32; i++){
      int f = w*32 + i;
      float4 wk = __ldg((const float4*)(Wk + f*128) + lane);
      float pp = wk.x*qv.x;
      pp = fmaf(wk.y, qv.y, pp);
      pp = fmaf(wk.z, qv.z, pp);
      pp = fmaf(wk.w, qv.w, pp);
      #pragma unroll
      for (int off = 16; off; off >>= 1)
        pp += __shfl_xor_sync(0xffffffffu, pp, off);
      if (lane == 0){
        s_qp[f] = pp;
        g_c1[b*(NSLOT*NF) + k*NF + f] = liw[f] * pp;
      }
    }
  }
  __syncthreads();

  // c2/c3
  {
    float a2 = liw[t]*s_qp[t], a3 = lib[t]*s_qp[t];
    #pragma unroll
    for (int off = 16; off; off >>= 1){
      a2 += __shfl_xor_sync(0xffffffffu, a2, off);
      a3 += __shfl_xor_sync(0xffffffffu, a3, off);
    }
    if ((t & 31) == 0){ s_red[t >> 5] = a2; s_red[16 + (t >> 5)] = a3; }
  }
  __syncthreads();
  if (t == 0){
    float a2 = 0.f, a3 = 0.f;
    #pragma unroll
    for (int i = 0; i < 8; i++){ a2 += s_red[i]; a3 += s_red[16 + i]; }
    g_c2[b*NSLOT + k] = a2;
    g_c3[b*NSLOT + k] = a3;
  }
}

// =====================================================================
// qprep0: init slots + first-iteration c1/c2/c3
// =====================================================================
__global__ void __launch_bounds__(384) qprep0(const float* __restrict__ si,
    float* __restrict__ slots,
    const float* __restrict__ Wq, const float* __restrict__ Wk,
    const float* __restrict__ lnqw, const float* __restrict__ lnqb,
    const float* __restrict__ liw, const float* __restrict__ lib){
  const int b = blockIdx.x, t = threadIdx.x;
  __shared__ float s_new[1024], s_lnq[1024], s_q[1024], s_qp[2048];
  __shared__ float smu[NSLOT], srs[NSLOT];
  for (int idx = t; idx < 1024; idx += 384){
    float v = si[idx];
    s_new[idx] = v;
    slots[b*1024 + idx] = v;
  }
  __syncthreads();
  if (t < NSLOT){
    float su = 0.f, sq = 0.f;
    for (int d = 0; d < ND; d++){ float x = s_new[t*ND + d]; su += x; sq = fmaf(x,x,sq); }
    float mu = su * (1.f/ND);
    smu[t] = mu; srs[t] = rsqrtf(sq*(1.f/ND) - mu*mu + 1e-5f);
  }
  __syncthreads();
  for (int idx = t; idx < 1024; idx += 384){
    int j = idx >> 7, d = idx & 127;
    s_lnq[idx] = (s_new[idx] - smu[j]) * srs[j] * lnqw[d] + lnqb[d];
  }
  __syncthreads();
  const float inv_scale = 0.08838834764831845f;
  for (int idx = t; idx < 1024; idx += 384){
    int j = idx >> 7, d = idx & 127;
    float a = 0.f;
    #pragma unroll 4
    for (int f = 0; f < ND; f++) a = fmaf(s_lnq[j*128 + f], Wq[f*128 + d], a);
    s_q[idx] = a * inv_scale;
  }
  __syncthreads();
  for (int idx = t; idx < 2048; idx += 384){
    int k = idx >> 8, f = idx & 255;
    float qp = 0.f;
    const float* qrow = s_q + k*128;
    const float* wrow = Wk + f*128;
    #pragma unroll 4
    for (int d = 0; d < ND; d++) qp = fmaf(qrow[d], wrow[d], qp);
    s_qp[idx] = qp;
    g_c1[b*2048 + idx] = liw[f] * qp;
  }
  __syncthreads();
  if (t < NSLOT){
    float a2 = 0.f, a3 = 0.f;
    for (int f = 0; f < 256; f++){
      a2 = fmaf(liw[f], s_qp[t*256 + f], a2);
      a3 = fmaf(lib[f], s_qp[t*256 + f], a3);
    }
    g_c2[b*NSLOT + t] = a2;
    g_c3[b*NSLOT + t] = a3;
  }
}

// ---------------- launch ----------------
extern "C" void kernel_launch(void* const* d_in, const int* in_sizes, int n_in,
                              void* d_out, int out_size){
  const float* inputs   = (const float*)d_in[0];
  const float* slotinit = (const float*)d_in[1];
  const float* Wq       = (const float*)d_in[2];
  const float* Wk       = (const float*)d_in[3];
  const float* Wv       = (const float*)d_in[4];
  const float* gru_wi   = (const float*)d_in[5];
  const float* gru_wh   = (const float*)d_in[6];
  const float* gru_bi   = (const float*)d_in[7];
  const float* gru_bh   = (const float*)d_in[8];
  const float* ln_in_w  = (const float*)d_in[9];
  const float* ln_in_b  = (const float*)d_in[10];
  const float* ln_s_w   = (const float*)d_in[11];
  const float* ln_s_b   = (const float*)d_in[12];
  const float* ln_m_w   = (const float*)d_in[13];
  const float* ln_m_b   = (const float*)d_in[14];
  const float* mlp_w1   = (const float*)d_in[15];
  const float* mlp_b1   = (const float*)d_in[16];
  const float* mlp_w2   = (const float*)d_in[17];
  const float* mlp_b2   = (const float*)d_in[18];
  float* out = (float*)d_out;

  qprep0<<<NB, 384>>>(slotinit, out, Wq, Wk, ln_s_w, ln_s_b, ln_in_w, ln_in_b); // 1
  dummy_k<<<1, 32>>>();                                                         // 2
  dummy_k<<<1, 32>>>();                                                         // 3

  for (int it = 0; it < 3; it++){
    attn_scan<<<dim3(NB, 32), 128>>>(inputs);   // 4th launch on it=0 (ncu)
    tail_bk<<<dim3(NB, NSLOT), 256>>>(out, gru_wi, gru_wh, gru_bi, gru_bh,
                           ln_m_w, ln_m_b, mlp_w1, mlp_b1, mlp_w2, mlp_b2,
                           Wq, Wk, Wv, ln_s_w, ln_s_b, ln_in_w, ln_in_b,
                           (it < 2) ? 1 : 0);
  }
}

// round 8
// speedup vs baseline: 2.2235x; 1.0991x over previous
#include <cuda_runtime.h>
#include <cstdint>

// Problem constants
#define NB 64
#define NN 4096
#define NF 256
#define ND 128
#define NSLOT 8
#define NCH 128                 // warp-chunks per batch (32 rows each)

// ---------------- device scratch ----------------
__device__ float g_part[(size_t)NB*NCH*NSLOT*NF];   // [b][wc][k][f]
__device__ float g_t2p[NB*NCH*NSLOT];
__device__ float g_t3p[NB*NCH*NSLOT];
__device__ float g_c1[NB*NSLOT*NF];                 // lw * q'   [b][k][f]
__device__ float g_c2[NB*NSLOT];
__device__ float g_c3[NB*NSLOT];
__device__ float2 g_stats[(size_t)NB*NN];           // {mu, rs} per row

__device__ __forceinline__ float sigm(float x){ return 1.f / (1.f + expf(-x)); }

// =====================================================================
// stats_k: per-row LN stats, once. Warp per row.
// =====================================================================
__global__ void __launch_bounds__(256) stats_k(const float* __restrict__ X){
  const int warp = threadIdx.x >> 5, lane = threadIdx.x & 31;
  const size_t row = (size_t)blockIdx.x * 8 + warp;
  const float4* xr = (const float4*)(X + row*NF);
  float4 x0 = __ldg(xr + lane);
  float4 x1 = __ldg(xr + 32 + lane);
  float s  = ((x0.x + x0.y) + (x0.z + x0.w)) + ((x1.x + x1.y) + (x1.z + x1.w));
  float q2 = x0.x*x0.x;
  q2 = fmaf(x0.y, x0.y, q2); q2 = fmaf(x0.z, x0.z, q2); q2 = fmaf(x0.w, x0.w, q2);
  q2 = fmaf(x1.x, x1.x, q2); q2 = fmaf(x1.y, x1.y, q2);
  q2 = fmaf(x1.z, x1.z, q2); q2 = fmaf(x1.w, x1.w, q2);
  #pragma unroll
  for (int off = 16; off; off >>= 1){
    s  += __shfl_xor_sync(0xffffffffu, s,  off);
    q2 += __shfl_xor_sync(0xffffffffu, q2, off);
  }
  if (lane == 0){
    float mu = s * (1.f/256.f);
    float rs = rsqrtf(fmaf(q2, 1.f/256.f, -mu*mu) + 1e-5f);
    g_stats[row] = make_float2(mu, rs);
  }
}

// =====================================================================
// attn_scan v5: register-resident, stats precomputed (8-value butterfly).
// Grid (NB, 32), 128 threads; wc = blockIdx.y*4 + warp.
// =====================================================================
__global__ void __launch_bounds__(128, 2) attn_scan(const float* __restrict__ X){
  const int b = blockIdx.x;
  const int warp = threadIdx.x >> 5, lane = threadIdx.x & 31;
  const int wc = blockIdx.y * 4 + warp;

  float4 c1a[NSLOT], c1b[NSLOT];
  float c2[NSLOT], c3[NSLOT];
  {
    const float* c1p = g_c1 + b*NSLOT*NF;
    #pragma unroll
    for (int k = 0; k < NSLOT; k++){
      c1a[k] = __ldg((const float4*)(c1p + k*NF) + lane);
      c1b[k] = __ldg((const float4*)(c1p + k*NF + 128) + lane);
      c2[k] = __ldg(g_c2 + b*NSLOT + k);
      c3[k] = __ldg(g_c3 + b*NSLOT + k);
    }
  }

  float4 A0[NSLOT], A1[NSLOT];
  float t2a[NSLOT], t3a[NSLOT];
  #pragma unroll
  for (int k = 0; k < NSLOT; k++){
    A0[k] = make_float4(0.f,0.f,0.f,0.f);
    A1[k] = make_float4(0.f,0.f,0.f,0.f);
    t2a[k] = 0.f; t3a[k] = 0.f;
  }

  const size_t row0 = (size_t)b*NN + (size_t)wc*32;
  const float* Xb = X + row0*NF;
  for (int r = 0; r < 32; r++){
    const float4* xr = (const float4*)(Xb + (size_t)r*NF);
    float4 x0 = __ldg(xr + lane);
    float4 x1 = __ldg(xr + 32 + lane);
    float2 st = __ldg(&g_stats[row0 + r]);   // {mu, rs}

    float p[NSLOT];
    #pragma unroll
    for (int k = 0; k < NSLOT; k++){
      float pk = x0.x*c1a[k].x;
      pk = fmaf(x0.y, c1a[k].y, pk);
      pk = fmaf(x0.z, c1a[k].z, pk);
      pk = fmaf(x0.w, c1a[k].w, pk);
      pk = fmaf(x1.x, c1b[k].x, pk);
      pk = fmaf(x1.y, c1b[k].y, pk);
      pk = fmaf(x1.z, c1b[k].z, pk);
      pk = fmaf(x1.w, c1b[k].w, pk);
      p[k] = pk;
    }
    #pragma unroll
    for (int off = 16; off; off >>= 1){
      #pragma unroll
      for (int k = 0; k < NSLOT; k++)
        p[k] += __shfl_xor_sync(0xffffffffu, p[k], off);
    }

    const float mu = st.x, rs = st.y;
    float lg[NSLOT];
    #pragma unroll
    for (int k = 0; k < NSLOT; k++)
      lg[k] = fmaf(rs, fmaf(-mu, c2[k], p[k]), c3[k]);
    float m = fmaxf(fmaxf(fmaxf(lg[0],lg[1]), fmaxf(lg[2],lg[3])),
                    fmaxf(fmaxf(lg[4],lg[5]), fmaxf(lg[6],lg[7])));
    float e[NSLOT], es = 0.f;
    #pragma unroll
    for (int k = 0; k < NSLOT; k++){ e[k] = __expf(lg[k] - m); es += e[k]; }
    float inv = __fdividef(1.f, es);

    #pragma unroll
    for (int k = 0; k < NSLOT; k++){
      float a  = fmaf(e[k], inv, 1e-8f);
      float ar = a * rs;
      t3a[k] += a;
      t2a[k] = fmaf(ar, mu, t2a[k]);
      A0[k].x = fmaf(ar, x0.x, A0[k].x);
      A0[k].y = fmaf(ar, x0.y, A0[k].y);
      A0[k].z = fmaf(ar, x0.z, A0[k].z);
      A0[k].w = fmaf(ar, x0.w, A0[k].w);
      A1[k].x = fmaf(ar, x1.x, A1[k].x);
      A1[k].y = fmaf(ar, x1.y, A1[k].y);
      A1[k].z = fmaf(ar, x1.z, A1[k].z);
      A1[k].w = fmaf(ar, x1.w, A1[k].w);
    }
  }

  float* gp = g_part + (size_t)((b*NCH + wc)*NSLOT)*NF;
  #pragma unroll
  for (int k = 0; k < NSLOT; k++){
    *(float4*)(gp + k*NF + lane*4)       = A0[k];
    *(float4*)(gp + k*NF + 128 + lane*4) = A1[k];
  }
  if (lane == 0){
    #pragma unroll
    for (int k = 0; k < NSLOT; k++){
      g_t2p[(b*NCH + wc)*NSLOT + k] = t2a[k];
      g_t3p[(b*NCH + wc)*NSLOT + k] = t3a[k];
    }
  }
}

// =====================================================================
// tail_bk v2: explicit load batching (MLP 16) in every GEMV.
// Grid (NB, NSLOT), 256 threads.
// =====================================================================
__global__ void __launch_bounds__(256) tail_bk(float* __restrict__ slots,
    const float* __restrict__ wi, const float* __restrict__ wh,
    const float* __restrict__ bi, const float* __restrict__ bh,
    const float* __restrict__ lnw, const float* __restrict__ lnb,   // ln_mlp
    const float* __restrict__ w1, const float* __restrict__ b1,
    const float* __restrict__ w2, const float* __restrict__ b2,
    const float* __restrict__ Wq, const float* __restrict__ Wk,
    const float* __restrict__ Wv,
    const float* __restrict__ lnqw, const float* __restrict__ lnqb, // ln_slots
    const float* __restrict__ liw, const float* __restrict__ lib,   // ln_in
    int do_q){
  const int b = blockIdx.x, k = blockIdx.y, t = threadIdx.x;
  __shared__ __align__(16) float s_wt[256];
  __shared__ float s_sp[128], s_upd[128], s_gx[384], s_gh[384];
  __shared__ float s_mid[128], s_ln[128], s_h[256], s_new[128];
  __shared__ __align__(16) float s_q[128];
  __shared__ float s_qp[256];
  __shared__ float s_red[256];
  __shared__ float s_sc[8];

  if (t < 128) s_sp[t] = slots[b*1024 + k*128 + t];

  // t2/t3 totals over 128 chunks — warp-parallel
  if (t < 64){
    int w = t >> 5, lane = t & 31;
    const float* src = w ? g_t3p : g_t2p;
    float a = 0.f;
    #pragma unroll
    for (int j = 0; j < 4; j++)
      a += __ldg(src + (b*NCH + lane*4 + j)*NSLOT + k);
    #pragma unroll
    for (int off = 16; off; off >>= 1)
      a += __shfl_xor_sync(0xffffffffu, a, off);
    if (lane == 0) s_sc[w] = a;
  }
  __syncthreads();
  const float st2 = s_sc[0], st3 = s_sc[1];

  // weighted[f] = liw*(t1 - t2) + lib*t3  (batched strided reduce)
  {
    const float* gp = g_part + (size_t)(b*NCH*NSLOT)*NF + k*NF + t;
    float acc = 0.f;
    for (int cb = 0; cb < NCH; cb += 16){
      float v[16];
      #pragma unroll
      for (int j = 0; j < 16; j++) v[j] = __ldg(gp + (size_t)(cb+j)*NSLOT*NF);
      #pragma unroll
      for (int j = 0; j < 16; j++) acc += v[j];
    }
    s_wt[t] = liw[t]*(acc - st2) + lib[t]*st3;
  }
  __syncthreads();

  // updates[d] = (weighted @ Wv)/t3   (2 threads/d, batched)
  {
    int d = t & 127, h = t >> 7;
    float u = 0.f;
    for (int fb = h*128; fb < h*128 + 128; fb += 16){
      float v[16];
      #pragma unroll
      for (int j = 0; j < 16; j++) v[j] = __ldg(Wv + (fb+j)*128 + d);
      #pragma unroll
      for (int j = 0; j < 16; j++) u = fmaf(s_wt[fb+j], v[j], u);
    }
    s_red[t] = u;
  }
  __syncthreads();
  if (t < 128) s_upd[t] = (s_red[t] + s_red[t + 128]) / st3;
  __syncthreads();

  // GRU gates (batched)
  {
    float ax = bi[t], ah = bh[t];
    for (int fb = 0; fb < 128; fb += 16){
      float a_[16], h_[16];
      #pragma unroll
      for (int j = 0; j < 16; j++){
        a_[j] = __ldg(wi + (fb+j)*384 + t);
        h_[j] = __ldg(wh + (fb+j)*384 + t);
      }
      #pragma unroll
      for (int j = 0; j < 16; j++){
        ax = fmaf(s_upd[fb+j], a_[j], ax);
        ah = fmaf(s_sp[fb+j],  h_[j], ah);
      }
    }
    s_gx[t] = ax; s_gh[t] = ah;
  }
  if (t < 128){
    int g = 256 + t;
    float ax = bi[g], ah = bh[g];
    for (int fb = 0; fb < 128; fb += 16){
      float a_[16], h_[16];
      #pragma unroll
      for (int j = 0; j < 16; j++){
        a_[j] = __ldg(wi + (fb+j)*384 + g);
        h_[j] = __ldg(wh + (fb+j)*384 + g);
      }
      #pragma unroll
      for (int j = 0; j < 16; j++){
        ax = fmaf(s_upd[fb+j], a_[j], ax);
        ah = fmaf(s_sp[fb+j],  h_[j], ah);
      }
    }
    s_gx[g] = ax; s_gh[g] = ah;
  }
  __syncthreads();

  if (t < 128){
    float r = sigm(s_gx[t] + s_gh[t]);
    float z = sigm(s_gx[128 + t] + s_gh[128 + t]);
    float n = tanhf(fmaf(r, s_gh[256 + t], s_gx[256 + t]));
    s_mid[t] = (1.f - z)*n + z*s_sp[t];
  }
  __syncthreads();

  // LN(mid)
  if (t < 128){
    float x = s_mid[t], xs = x, xq = x*x;
    #pragma unroll
    for (int off = 16; off; off >>= 1){
      xs += __shfl_xor_sync(0xffffffffu, xs, off);
      xq += __shfl_xor_sync(0xffffffffu, xq, off);
    }
    if ((t & 31) == 0){ s_red[t >> 5] = xs; s_red[8 + (t >> 5)] = xq; }
  }
  __syncthreads();
  if (t == 0){
    float su = s_red[0]+s_red[1]+s_red[2]+s_red[3];
    float sq = s_red[8]+s_red[9]+s_red[10]+s_red[11];
    float mu = su * (1.f/128.f);
    s_sc[2] = mu; s_sc[3] = rsqrtf(sq*(1.f/128.f) - mu*mu + 1e-5f);
  }
  __syncthreads();
  if (t < 128) s_ln[t] = (s_mid[t] - s_sc[2])*s_sc[3]*lnw[t] + lnb[t];
  __syncthreads();

  // hidden[c] = relu(ln @ w1 + b1)  (batched)
  {
    float h = b1[t];
    for (int fb = 0; fb < 128; fb += 16){
      float v[16];
      #pragma unroll
      for (int j = 0; j < 16; j++) v[j] = __ldg(w1 + (fb+j)*256 + t);
      #pragma unroll
      for (int j = 0; j < 16; j++) h = fmaf(s_ln[fb+j], v[j], h);
    }
    s_h[t] = fmaxf(h, 0.f);
  }
  __syncthreads();

  // out[d] = mid + hidden @ w2 + b2  (2 threads/d, batched)
  {
    int d = t & 127, hh = t >> 7;
    float o = 0.f;
    for (int cb = hh*128; cb < hh*128 + 128; cb += 16){
      float v[16];
      #pragma unroll
      for (int j = 0; j < 16; j++) v[j] = __ldg(w2 + (cb+j)*128 + d);
      #pragma unroll
      for (int j = 0; j < 16; j++) o = fmaf(s_h[cb+j], v[j], o);
    }
    s_red[t] = o;
  }
  __syncthreads();
  if (t < 128){
    float o = s_mid[t] + b2[t] + s_red[t] + s_red[t + 128];
    slots[b*1024 + k*128 + t] = o;
    s_new[t] = o;
  }
  if (!do_q) return;
  __syncthreads();

  // LN(new) with ln_slots
  if (t < 128){
    float x = s_new[t], xs = x, xq = x*x;
    #pragma unroll
    for (int off = 16; off; off >>= 1){
      xs += __shfl_xor_sync(0xffffffffu, xs, off);
      xq += __shfl_xor_sync(0xffffffffu, xq, off);
    }
    if ((t & 31) == 0){ s_red[t >> 5] = xs; s_red[8 + (t >> 5)] = xq; }
  }
  __syncthreads();
  if (t == 0){
    float su = s_red[0]+s_red[1]+s_red[2]+s_red[3];
    float sq = s_red[8]+s_red[9]+s_red[10]+s_red[11];
    float mu = su * (1.f/128.f);
    s_sc[4] = mu; s_sc[5] = rsqrtf(sq*(1.f/128.f) - mu*mu + 1e-5f);
  }
  __syncthreads();
  if (t < 128) s_ln[t] = (s_new[t] - s_sc[4])*s_sc[5]*lnqw[t] + lnqb[t];
  __syncthreads();

  // q[d] = (lnq @ Wq) * 1/sqrt(D)  (batched)
  if (t < 128){
    float a = 0.f;
    for (int fb = 0; fb < 128; fb += 16){
      float v[16];
      #pragma unroll
      for (int j = 0; j < 16; j++) v[j] = __ldg(Wq + (fb+j)*128 + t);
      #pragma unroll
      for (int j = 0; j < 16; j++) a = fmaf(s_ln[fb+j], v[j], a);
    }
    s_q[t] = a * 0.08838834764831845f;
  }
  __syncthreads();

  // q'[f] = Wk[f,:] . q  (warp per 32 f, 4-way interleaved butterflies)
  {
    int w = t >> 5, lane = t & 31;
    float4 qv = ((const float4*)s_q)[lane];
    for (int i = 0; i < 32; i += 4){
      float pp[4];
      #pragma unroll
      for (int j = 0; j < 4; j++){
        int f = w*32 + i + j;
        float4 wk = __ldg((const float4*)(Wk + f*128) + lane);
        float v = wk.x*qv.x;
        v = fmaf(wk.y, qv.y, v);
        v = fmaf(wk.z, qv.z, v);
        v = fmaf(wk.w, qv.w, v);
        pp[j] = v;
      }
      #pragma unroll
      for (int off = 16; off; off >>= 1)
        #pragma unroll
        for (int j = 0; j < 4; j++)
          pp[j] += __shfl_xor_sync(0xffffffffu, pp[j], off);
      if (lane == 0){
        #pragma unroll
        for (int j = 0; j < 4; j++){
          int f = w*32 + i + j;
          s_qp[f] = pp[j];
          g_c1[b*(NSLOT*NF) + k*NF + f] = liw[f] * pp[j];
        }
      }
    }
  }
  __syncthreads();

  // c2/c3
  {
    float a2 = liw[t]*s_qp[t], a3 = lib[t]*s_qp[t];
    #pragma unroll
    for (int off = 16; off; off >>= 1){
      a2 += __shfl_xor_sync(0xffffffffu, a2, off);
      a3 += __shfl_xor_sync(0xffffffffu, a3, off);
    }
    if ((t & 31) == 0){ s_red[t >> 5] = a2; s_red[16 + (t >> 5)] = a3; }
  }
  __syncthreads();
  if (t == 0){
    float a2 = 0.f, a3 = 0.f;
    #pragma unroll
    for (int i = 0; i < 8; i++){ a2 += s_red[i]; a3 += s_red[16 + i]; }
    g_c2[b*NSLOT + k] = a2;
    g_c3[b*NSLOT + k] = a3;
  }
}

// =====================================================================
// qprep0: init slots + first-iteration c1/c2/c3 (batched loads)
// =====================================================================
__global__ void __launch_bounds__(384) qprep0(const float* __restrict__ si,
    float* __restrict__ slots,
    const float* __restrict__ Wq, const float* __restrict__ Wk,
    const float* __restrict__ lnqw, const float* __restrict__ lnqb,
    const float* __restrict__ liw, const float* __restrict__ lib){
  const int b = blockIdx.x, t = threadIdx.x;
  __shared__ float s_new[1024], s_lnq[1024], s_q[1024], s_qp[2048];
  __shared__ float smu[NSLOT], srs[NSLOT];
  for (int idx = t; idx < 1024; idx += 384){
    float v = si[idx];
    s_new[idx] = v;
    slots[b*1024 + idx] = v;
  }
  __syncthreads();
  if (t < NSLOT){
    float su = 0.f, sq = 0.f;
    for (int d = 0; d < ND; d++){ float x = s_new[t*ND + d]; su += x; sq = fmaf(x,x,sq); }
    float mu = su * (1.f/ND);
    smu[t] = mu; srs[t] = rsqrtf(sq*(1.f/ND) - mu*mu + 1e-5f);
  }
  __syncthreads();
  for (int idx = t; idx < 1024; idx += 384){
    int j = idx >> 7, d = idx & 127;
    s_lnq[idx] = (s_new[idx] - smu[j]) * srs[j] * lnqw[d] + lnqb[d];
  }
  __syncthreads();
  const float inv_scale = 0.08838834764831845f;
  for (int idx = t; idx < 1024; idx += 384){
    int j = idx >> 7, d = idx & 127;
    float a = 0.f;
    for (int fb = 0; fb < 128; fb += 8){
      float v[8];
      #pragma unroll
      for (int u = 0; u < 8; u++) v[u] = __ldg(Wq + (fb+u)*128 + d);
      #pragma unroll
      for (int u = 0; u < 8; u++) a = fmaf(s_lnq[j*128 + fb+u], v[u], a);
    }
    s_q[idx] = a * inv_scale;
  }
  __syncthreads();
  for (int idx = t; idx < 2048; idx += 384){
    int k = idx >> 8, f = idx & 255;
    float qp = 0.f;
    const float* qrow = s_q + k*128;
    const float* wrow = Wk + f*128;
    for (int fb = 0; fb < 128; fb += 8){
      float v[8];
      #pragma unroll
      for (int u = 0; u < 8; u++) v[u] = __ldg(wrow + fb + u);
      #pragma unroll
      for (int u = 0; u < 8; u++) qp = fmaf(qrow[fb+u], v[u], qp);
    }
    s_qp[idx] = qp;
    g_c1[b*2048 + idx] = liw[f] * qp;
  }
  __syncthreads();
  if (t < NSLOT){
    float a2 = 0.f, a3 = 0.f;
    for (int f = 0; f < 256; f++){
      a2 = fmaf(liw[f], s_qp[t*256 + f], a2);
      a3 = fmaf(lib[f], s_qp[t*256 + f], a3);
    }
    g_c2[b*NSLOT + t] = a2;
    g_c3[b*NSLOT + t] = a3;
  }
}

// ---------------- launch ----------------
extern "C" void kernel_launch(void* const* d_in, const int* in_sizes, int n_in,
                              void* d_out, int out_size){
  const float* inputs   = (const float*)d_in[0];
  const float* slotinit = (const float*)d_in[1];
  const float* Wq       = (const float*)d_in[2];
  const float* Wk       = (const float*)d_in[3];
  const float* Wv       = (const float*)d_in[4];
  const float* gru_wi   = (const float*)d_in[5];
  const float* gru_wh   = (const float*)d_in[6];
  const float* gru_bi   = (const float*)d_in[7];
  const float* gru_bh   = (const float*)d_in[8];
  const float* ln_in_w  = (const float*)d_in[9];
  const float* ln_in_b  = (const float*)d_in[10];
  const float* ln_s_w   = (const float*)d_in[11];
  const float* ln_s_b   = (const float*)d_in[12];
  const float* ln_m_w   = (const float*)d_in[13];
  const float* ln_m_b   = (const float*)d_in[14];
  const float* mlp_w1   = (const float*)d_in[15];
  const float* mlp_b1   = (const float*)d_in[16];
  const float* mlp_w2   = (const float*)d_in[17];
  const float* mlp_b2   = (const float*)d_in[18];
  float* out = (float*)d_out;

  qprep0<<<NB, 384>>>(slotinit, out, Wq, Wk, ln_s_w, ln_s_b, ln_in_w, ln_in_b); // 1
  stats_k<<<(NB*NN)/8, 256>>>(inputs);                                          // 2

  for (int it = 0; it < 3; it++){
    attn_scan<<<dim3(NB, 32), 128>>>(inputs);   // 3rd launch on it=0
    tail_bk<<<dim3(NB, NSLOT), 256>>>(out, gru_wi, gru_wh, gru_bi, gru_bh,     // 4th = ncu target
                           ln_m_w, ln_m_b, mlp_w1, mlp_b1, mlp_w2, mlp_b2,
                           Wq, Wk, Wv, ln_s_w, ln_s_b, ln_in_w, ln_in_b,
                           (it < 2) ? 1 : 0);
  }
}

// round 10
// speedup vs baseline: 2.9591x; 1.3309x over previous
#include <cuda_runtime.h>
#include <cstdint>

// Problem constants
#define NB 64
#define NN 4096
#define NF 256
#define ND 128
#define NSLOT 8
#define NCH 32                  // block-chunks per batch (128 rows each)

// ---------------- device scratch ----------------
__device__ float g_part[(size_t)NB*NCH*NSLOT*NF];   // [b][c][k][f]  (16.8MB)
__device__ float g_t2p[NB*NCH*NSLOT];
__device__ float g_t3p[NB*NCH*NSLOT];
__device__ float g_c1[NB*NSLOT*NF];                 // lw * q'   [b][k][f]
__device__ float g_c2[NB*NSLOT];
__device__ float g_c3[NB*NSLOT];
__device__ float2 g_stats[(size_t)NB*NN];           // {mu, rs} per row

__device__ __forceinline__ float sigm(float x){ return 1.f / (1.f + expf(-x)); }

__global__ void dummy_k(){}

// =====================================================================
// stats_k: per-row LN stats, once. Warp per row.
// =====================================================================
__global__ void __launch_bounds__(256) stats_k(const float* __restrict__ X){
  const int warp = threadIdx.x >> 5, lane = threadIdx.x & 31;
  const size_t row = (size_t)blockIdx.x * 8 + warp;
  const float4* xr = (const float4*)(X + row*NF);
  float4 x0 = __ldg(xr + lane);
  float4 x1 = __ldg(xr + 32 + lane);
  float s  = ((x0.x + x0.y) + (x0.z + x0.w)) + ((x1.x + x1.y) + (x1.z + x1.w));
  float q2 = x0.x*x0.x;
  q2 = fmaf(x0.y, x0.y, q2); q2 = fmaf(x0.z, x0.z, q2); q2 = fmaf(x0.w, x0.w, q2);
  q2 = fmaf(x1.x, x1.x, q2); q2 = fmaf(x1.y, x1.y, q2);
  q2 = fmaf(x1.z, x1.z, q2); q2 = fmaf(x1.w, x1.w, q2);
  #pragma unroll
  for (int off = 16; off; off >>= 1){
    s  += __shfl_xor_sync(0xffffffffu, s,  off);
    q2 += __shfl_xor_sync(0xffffffffu, q2, off);
  }
  if (lane == 0){
    float mu = s * (1.f/256.f);
    float rs = rsqrtf(fmaf(q2, 1.f/256.f, -mu*mu) + 1e-5f);
    g_stats[row] = make_float2(mu, rs);
  }
}

// =====================================================================
// attn_scan v6: c1 in smem (loaded per-k per 2 rows), 2-row interleave,
// block-level combine -> NCH=32 chunks of 128 rows.
// Grid (NB, 32), 128 threads (4 warps x 32 rows).
// =====================================================================
__global__ void __launch_bounds__(128, 3) attn_scan(const float* __restrict__ X){
  const int b = blockIdx.x, blk = blockIdx.y;
  const int tid = threadIdx.x;
  const int warp = tid >> 5, lane = tid & 31;

  __shared__ __align__(16) float s_c1[NSLOT*NF];      // 8KB
  __shared__ __align__(16) float s_buf[4][NSLOT*NF];  // 32KB
  __shared__ float s_t23[4][16];

  for (int i = tid; i < NSLOT*NF; i += 128) s_c1[i] = __ldg(g_c1 + b*NSLOT*NF + i);
  float c2[NSLOT], c3[NSLOT];
  #pragma unroll
  for (int k = 0; k < NSLOT; k++){
    c2[k] = __ldg(g_c2 + b*NSLOT + k);
    c3[k] = __ldg(g_c3 + b*NSLOT + k);
  }
  __syncthreads();

  float4 A0[NSLOT], A1[NSLOT];
  float t2a[NSLOT], t3a[NSLOT];
  #pragma unroll
  for (int k = 0; k < NSLOT; k++){
    A0[k] = make_float4(0.f,0.f,0.f,0.f);
    A1[k] = make_float4(0.f,0.f,0.f,0.f);
    t2a[k] = 0.f; t3a[k] = 0.f;
  }

  const size_t row0 = (size_t)b*NN + (size_t)blk*128 + (size_t)warp*32;
  const float* Xb = X + row0*NF;

  for (int r = 0; r < 32; r += 2){
    const float4* xr = (const float4*)(Xb + (size_t)r*NF);
    float4 x0 = __ldg(xr + lane);
    float4 x1 = __ldg(xr + 32 + lane);
    float4 y0 = __ldg(xr + 64 + lane);
    float4 y1 = __ldg(xr + 96 + lane);
    float2 stx = __ldg(&g_stats[row0 + r]);
    float2 sty = __ldg(&g_stats[row0 + r + 1]);

    float p[NSLOT], q[NSLOT];
    #pragma unroll
    for (int k = 0; k < NSLOT; k++){
      float4 ca = *(const float4*)(s_c1 + k*NF + lane*4);
      float4 cb = *(const float4*)(s_c1 + k*NF + 128 + lane*4);
      float pk = x0.x*ca.x;
      pk = fmaf(x0.y, ca.y, pk); pk = fmaf(x0.z, ca.z, pk); pk = fmaf(x0.w, ca.w, pk);
      pk = fmaf(x1.x, cb.x, pk); pk = fmaf(x1.y, cb.y, pk);
      pk = fmaf(x1.z, cb.z, pk); pk = fmaf(x1.w, cb.w, pk);
      p[k] = pk;
      float qk = y0.x*ca.x;
      qk = fmaf(y0.y, ca.y, qk); qk = fmaf(y0.z, ca.z, qk); qk = fmaf(y0.w, ca.w, qk);
      qk = fmaf(y1.x, cb.x, qk); qk = fmaf(y1.y, cb.y, qk);
      qk = fmaf(y1.z, cb.z, qk); qk = fmaf(y1.w, cb.w, qk);
      q[k] = qk;
    }
    // 16-value butterfly (latency hidden by 16-way ILP)
    #pragma unroll
    for (int off = 16; off; off >>= 1){
      #pragma unroll
      for (int k = 0; k < NSLOT; k++){
        p[k] += __shfl_xor_sync(0xffffffffu, p[k], off);
        q[k] += __shfl_xor_sync(0xffffffffu, q[k], off);
      }
    }

    // row r softmax + accumulate
    {
      const float mu = stx.x, rs = stx.y;
      float lg[NSLOT];
      #pragma unroll
      for (int k = 0; k < NSLOT; k++)
        lg[k] = fmaf(rs, fmaf(-mu, c2[k], p[k]), c3[k]);
      float m = fmaxf(fmaxf(fmaxf(lg[0],lg[1]), fmaxf(lg[2],lg[3])),
                      fmaxf(fmaxf(lg[4],lg[5]), fmaxf(lg[6],lg[7])));
      float e[NSLOT], es = 0.f;
      #pragma unroll
      for (int k = 0; k < NSLOT; k++){ e[k] = __expf(lg[k] - m); es += e[k]; }
      float inv = __fdividef(1.f, es);
      #pragma unroll
      for (int k = 0; k < NSLOT; k++){
        float a  = fmaf(e[k], inv, 1e-8f);
        float ar = a * rs;
        t3a[k] += a;
        t2a[k] = fmaf(ar, mu, t2a[k]);
        A0[k].x = fmaf(ar, x0.x, A0[k].x);
        A0[k].y = fmaf(ar, x0.y, A0[k].y);
        A0[k].z = fmaf(ar, x0.z, A0[k].z);
        A0[k].w = fmaf(ar, x0.w, A0[k].w);
        A1[k].x = fmaf(ar, x1.x, A1[k].x);
        A1[k].y = fmaf(ar, x1.y, A1[k].y);
        A1[k].z = fmaf(ar, x1.z, A1[k].z);
        A1[k].w = fmaf(ar, x1.w, A1[k].w);
      }
    }
    // row r+1 softmax + accumulate
    {
      const float mu = sty.x, rs = sty.y;
      float lg[NSLOT];
      #pragma unroll
      for (int k = 0; k < NSLOT; k++)
        lg[k] = fmaf(rs, fmaf(-mu, c2[k], q[k]), c3[k]);
      float m = fmaxf(fmaxf(fmaxf(lg[0],lg[1]), fmaxf(lg[2],lg[3])),
                      fmaxf(fmaxf(lg[4],lg[5]), fmaxf(lg[6],lg[7])));
      float e[NSLOT], es = 0.f;
      #pragma unroll
      for (int k = 0; k < NSLOT; k++){ e[k] = __expf(lg[k] - m); es += e[k]; }
      float inv = __fdividef(1.f, es);
      #pragma unroll
      for (int k = 0; k < NSLOT; k++){
        float a  = fmaf(e[k], inv, 1e-8f);
        float ar = a * rs;
        t3a[k] += a;
        t2a[k] = fmaf(ar, mu, t2a[k]);
        A0[k].x = fmaf(ar, y0.x, A0[k].x);
        A0[k].y = fmaf(ar, y0.y, A0[k].y);
        A0[k].z = fmaf(ar, y0.z, A0[k].z);
        A0[k].w = fmaf(ar, y0.w, A0[k].w);
        A1[k].x = fmaf(ar, y1.x, A1[k].x);
        A1[k].y = fmaf(ar, y1.y, A1[k].y);
        A1[k].z = fmaf(ar, y1.z, A1[k].z);
        A1[k].w = fmaf(ar, y1.w, A1[k].w);
      }
    }
  }

  // block combine: each warp dumps A to its smem buffer, then parallel sum
  #pragma unroll
  for (int k = 0; k < NSLOT; k++){
    *(float4*)(s_buf[warp] + k*NF + lane*4)       = A0[k];
    *(float4*)(s_buf[warp] + k*NF + 128 + lane*4) = A1[k];
  }
  if (lane == 0){
    #pragma unroll
    for (int k = 0; k < NSLOT; k++){
      s_t23[warp][k]     = t2a[k];
      s_t23[warp][8 + k] = t3a[k];
    }
  }
  __syncthreads();

  float* gp = g_part + (size_t)((b*NCH + blk)*NSLOT)*NF;
  #pragma unroll
  for (int j = 0; j < 4; j++){
    int off = (tid + j*128) * 4;
    float4 v0 = *(const float4*)(s_buf[0] + off);
    float4 v1 = *(const float4*)(s_buf[1] + off);
    float4 v2 = *(const float4*)(s_buf[2] + off);
    float4 v3 = *(const float4*)(s_buf[3] + off);
    float4 v;
    v.x = (v0.x + v1.x) + (v2.x + v3.x);
    v.y = (v0.y + v1.y) + (v2.y + v3.y);
    v.z = (v0.z + v1.z) + (v2.z + v3.z);
    v.w = (v0.w + v1.w) + (v2.w + v3.w);
    *(float4*)(gp + off) = v;
  }
  if (tid < 16){
    float v = s_t23[0][tid] + s_t23[1][tid] + s_t23[2][tid] + s_t23[3][tid];
    if (tid < 8) g_t2p[(b*NCH + blk)*NSLOT + tid]       = v;
    else         g_t3p[(b*NCH + blk)*NSLOT + (tid - 8)] = v;
  }
}

// =====================================================================
// tail_bk v3: NCH=32, batched loads. Grid (NB, NSLOT), 256 threads.
// =====================================================================
__global__ void __launch_bounds__(256) tail_bk(float* __restrict__ slots,
    const float* __restrict__ wi, const float* __restrict__ wh,
    const float* __restrict__ bi, const float* __restrict__ bh,
    const float* __restrict__ lnw, const float* __restrict__ lnb,   // ln_mlp
    const float* __restrict__ w1, const float* __restrict__ b1,
    const float* __restrict__ w2, const float* __restrict__ b2,
    const float* __restrict__ Wq, const float* __restrict__ Wk,
    const float* __restrict__ Wv,
    const float* __restrict__ lnqw, const float* __restrict__ lnqb, // ln_slots
    const float* __restrict__ liw, const float* __restrict__ lib,   // ln_in
    int do_q){
  const int b = blockIdx.x, k = blockIdx.y, t = threadIdx.x;
  __shared__ __align__(16) float s_wt[256];
  __shared__ float s_sp[128], s_upd[128], s_gx[384], s_gh[384];
  __shared__ float s_mid[128], s_ln[128], s_h[256], s_new[128];
  __shared__ __align__(16) float s_q[128];
  __shared__ float s_qp[256];
  __shared__ float s_red[256];
  __shared__ float s_sc[8];

  if (t < 128) s_sp[t] = slots[b*1024 + k*128 + t];

  // t2/t3 totals over 32 chunks — warp 0 / warp 1
  if (t < 64){
    int w = t >> 5, lane = t & 31;
    const float* src = w ? g_t3p : g_t2p;
    float a = __ldg(src + (b*NCH + lane)*NSLOT + k);
    #pragma unroll
    for (int off = 16; off; off >>= 1)
      a += __shfl_xor_sync(0xffffffffu, a, off);
    if (lane == 0) s_sc[w] = a;
  }
  __syncthreads();
  const float st2 = s_sc[0], st3 = s_sc[1];

  // weighted[f] = liw*(t1 - t2) + lib*t3  (32-chunk batched reduce)
  {
    const float* gp = g_part + (size_t)(b*NCH*NSLOT)*NF + k*NF + t;
    float acc = 0.f;
    #pragma unroll
    for (int cb = 0; cb < NCH; cb += 16){
      float v[16];
      #pragma unroll
      for (int j = 0; j < 16; j++) v[j] = __ldg(gp + (size_t)(cb+j)*NSLOT*NF);
      #pragma unroll
      for (int j = 0; j < 16; j++) acc += v[j];
    }
    s_wt[t] = liw[t]*(acc - st2) + lib[t]*st3;
  }
  __syncthreads();

  // updates[d] = (weighted @ Wv)/t3   (2 threads/d, batched)
  {
    int d = t & 127, h = t >> 7;
    float u = 0.f;
    for (int fb = h*128; fb < h*128 + 128; fb += 16){
      float v[16];
      #pragma unroll
      for (int j = 0; j < 16; j++) v[j] = __ldg(Wv + (fb+j)*128 + d);
      #pragma unroll
      for (int j = 0; j < 16; j++) u = fmaf(s_wt[fb+j], v[j], u);
    }
    s_red[t] = u;
  }
  __syncthreads();
  if (t < 128) s_upd[t] = (s_red[t] + s_red[t + 128]) / st3;
  __syncthreads();

  // GRU gates (batched, 32 loads in flight)
  {
    float ax = bi[t], ah = bh[t];
    for (int fb = 0; fb < 128; fb += 16){
      float a_[16], h_[16];
      #pragma unroll
      for (int j = 0; j < 16; j++){
        a_[j] = __ldg(wi + (fb+j)*384 + t);
        h_[j] = __ldg(wh + (fb+j)*384 + t);
      }
      #pragma unroll
      for (int j = 0; j < 16; j++){
        ax = fmaf(s_upd[fb+j], a_[j], ax);
        ah = fmaf(s_sp[fb+j],  h_[j], ah);
      }
    }
    s_gx[t] = ax; s_gh[t] = ah;
  }
  if (t < 128){
    int g = 256 + t;
    float ax = bi[g], ah = bh[g];
    for (int fb = 0; fb < 128; fb += 16){
      float a_[16], h_[16];
      #pragma unroll
      for (int j = 0; j < 16; j++){
        a_[j] = __ldg(wi + (fb+j)*384 + g);
        h_[j] = __ldg(wh + (fb+j)*384 + g);
      }
      #pragma unroll
      for (int j = 0; j < 16; j++){
        ax = fmaf(s_upd[fb+j], a_[j], ax);
        ah = fmaf(s_sp[fb+j],  h_[j], ah);
      }
    }
    s_gx[g] = ax; s_gh[g] = ah;
  }
  __syncthreads();

  if (t < 128){
    float r = sigm(s_gx[t] + s_gh[t]);
    float z = sigm(s_gx[128 + t] + s_gh[128 + t]);
    float n = tanhf(fmaf(r, s_gh[256 + t], s_gx[256 + t]));
    s_mid[t] = (1.f - z)*n + z*s_sp[t];
  }
  __syncthreads();

  // LN(mid)
  if (t < 128){
    float x = s_mid[t], xs = x, xq = x*x;
    #pragma unroll
    for (int off = 16; off; off >>= 1){
      xs += __shfl_xor_sync(0xffffffffu, xs, off);
      xq += __shfl_xor_sync(0xffffffffu, xq, off);
    }
    if ((t & 31) == 0){ s_red[t >> 5] = xs; s_red[8 + (t >> 5)] = xq; }
  }
  __syncthreads();
  if (t == 0){
    float su = s_red[0]+s_red[1]+s_red[2]+s_red[3];
    float sq = s_red[8]+s_red[9]+s_red[10]+s_red[11];
    float mu = su * (1.f/128.f);
    s_sc[2] = mu; s_sc[3] = rsqrtf(sq*(1.f/128.f) - mu*mu + 1e-5f);
  }
  __syncthreads();
  if (t < 128) s_ln[t] = (s_mid[t] - s_sc[2])*s_sc[3]*lnw[t] + lnb[t];
  __syncthreads();

  // hidden[c] = relu(ln @ w1 + b1)
  {
    float h = b1[t];
    for (int fb = 0; fb < 128; fb += 16){
      float v[16];
      #pragma unroll
      for (int j = 0; j < 16; j++) v[j] = __ldg(w1 + (fb+j)*256 + t);
      #pragma unroll
      for (int j = 0; j < 16; j++) h = fmaf(s_ln[fb+j], v[j], h);
    }
    s_h[t] = fmaxf(h, 0.f);
  }
  __syncthreads();

  // out[d] = mid + hidden @ w2 + b2  (2 threads/d)
  {
    int d = t & 127, hh = t >> 7;
    float o = 0.f;
    for (int cb = hh*128; cb < hh*128 + 128; cb += 16){
      float v[16];
      #pragma unroll
      for (int j = 0; j < 16; j++) v[j] = __ldg(w2 + (cb+j)*128 + d);
      #pragma unroll
      for (int j = 0; j < 16; j++) o = fmaf(s_h[cb+j], v[j], o);
    }
    s_red[t] = o;
  }
  __syncthreads();
  if (t < 128){
    float o = s_mid[t] + b2[t] + s_red[t] + s_red[t + 128];
    slots[b*1024 + k*128 + t] = o;
    s_new[t] = o;
  }
  if (!do_q) return;
  __syncthreads();

  // LN(new) with ln_slots
  if (t < 128){
    float x = s_new[t], xs = x, xq = x*x;
    #pragma unroll
    for (int off = 16; off; off >>= 1){
      xs += __shfl_xor_sync(0xffffffffu, xs, off);
      xq += __shfl_xor_sync(0xffffffffu, xq, off);
    }
    if ((t & 31) == 0){ s_red[t >> 5] = xs; s_red[8 + (t >> 5)] = xq; }
  }
  __syncthreads();
  if (t == 0){
    float su = s_red[0]+s_red[1]+s_red[2]+s_red[3];
    float sq = s_red[8]+s_red[9]+s_red[10]+s_red[11];
    float mu = su * (1.f/128.f);
    s_sc[4] = mu; s_sc[5] = rsqrtf(sq*(1.f/128.f) - mu*mu + 1e-5f);
  }
  __syncthreads();
  if (t < 128) s_ln[t] = (s_new[t] - s_sc[4])*s_sc[5]*lnqw[t] + lnqb[t];
  __syncthreads();

  // q[d] = (lnq @ Wq) * 1/sqrt(D)
  if (t < 128){
    float a = 0.f;
    for (int fb = 0; fb < 128; fb += 16){
      float v[16];
      #pragma unroll
      for (int j = 0; j < 16; j++) v[j] = __ldg(Wq + (fb+j)*128 + t);
      #pragma unroll
      for (int j = 0; j < 16; j++) a = fmaf(s_ln[fb+j], v[j], a);
    }
    s_q[t] = a * 0.08838834764831845f;
  }
  __syncthreads();

  // q'[f] = Wk[f,:] . q  (warp per 32 f, 4-way interleaved butterflies)
  {
    int w = t >> 5, lane = t & 31;
    float4 qv = ((const float4*)s_q)[lane];
    for (int i = 0; i < 32; i += 4){
      float pp[4];
      #pragma unroll
      for (int j = 0; j < 4; j++){
        int f = w*32 + i + j;
        float4 wk = __ldg((const float4*)(Wk + f*128) + lane);
        float v = wk.x*qv.x;
        v = fmaf(wk.y, qv.y, v);
        v = fmaf(wk.z, qv.z, v);
        v = fmaf(wk.w, qv.w, v);
        pp[j] = v;
      }
      #pragma unroll
      for (int off = 16; off; off >>= 1)
        #pragma unroll
        for (int j = 0; j < 4; j++)
          pp[j] += __shfl_xor_sync(0xffffffffu, pp[j], off);
      if (lane == 0){
        #pragma unroll
        for (int j = 0; j < 4; j++){
          int f = w*32 + i + j;
          s_qp[f] = pp[j];
          g_c1[b*(NSLOT*NF) + k*NF + f] = liw[f] * pp[j];
        }
      }
    }
  }
  __syncthreads();

  // c2/c3
  {
    float a2 = liw[t]*s_qp[t], a3 = lib[t]*s_qp[t];
    #pragma unroll
    for (int off = 16; off; off >>= 1){
      a2 += __shfl_xor_sync(0xffffffffu, a2, off);
      a3 += __shfl_xor_sync(0xffffffffu, a3, off);
    }
    if ((t & 31) == 0){ s_red[t >> 5] = a2; s_red[16 + (t >> 5)] = a3; }
  }
  __syncthreads();
  if (t == 0){
    float a2 = 0.f, a3 = 0.f;
    #pragma unroll
    for (int i = 0; i < 8; i++){ a2 += s_red[i]; a3 += s_red[16 + i]; }
    g_c2[b*NSLOT + k] = a2;
    g_c3[b*NSLOT + k] = a3;
  }
}

// =====================================================================
// qprep0: init slots + first-iteration c1/c2/c3 (batched loads)
// =====================================================================
__global__ void __launch_bounds__(384) qprep0(const float* __restrict__ si,
    float* __restrict__ slots,
    const float* __restrict__ Wq, const float* __restrict__ Wk,
    const float* __restrict__ lnqw, const float* __restrict__ lnqb,
    const float* __restrict__ liw, const float* __restrict__ lib){
  const int b = blockIdx.x, t = threadIdx.x;
  __shared__ float s_new[1024], s_lnq[1024], s_q[1024], s_qp[2048];
  __shared__ float smu[NSLOT], srs[NSLOT];
  for (int idx = t; idx < 1024; idx += 384){
    float v = si[idx];
    s_new[idx] = v;
    slots[b*1024 + idx] = v;
  }
  __syncthreads();
  if (t < NSLOT){
    float su = 0.f, sq = 0.f;
    for (int d = 0; d < ND; d++){ float x = s_new[t*ND + d]; su += x; sq = fmaf(x,x,sq); }
    float mu = su * (1.f/ND);
    smu[t] = mu; srs[t] = rsqrtf(sq*(1.f/ND) - mu*mu + 1e-5f);
  }
  __syncthreads();
  for (int idx = t; idx < 1024; idx += 384){
    int j = idx >> 7, d = idx & 127;
    s_lnq[idx] = (s_new[idx] - smu[j]) * srs[j] * lnqw[d] + lnqb[d];
  }
  __syncthreads();
  const float inv_scale = 0.08838834764831845f;
  for (int idx = t; idx < 1024; idx += 384){
    int j = idx >> 7, d = idx & 127;
    float a = 0.f;
    for (int fb = 0; fb < 128; fb += 8){
      float v[8];
      #pragma unroll
      for (int u = 0; u < 8; u++) v[u] = __ldg(Wq + (fb+u)*128 + d);
      #pragma unroll
      for (int u = 0; u < 8; u++) a = fmaf(s_lnq[j*128 + fb+u], v[u], a);
    }
    s_q[idx] = a * inv_scale;
  }
  __syncthreads();
  for (int idx = t; idx < 2048; idx += 384){
    int k = idx >> 8, f = idx & 255;
    float qp = 0.f;
    const float* qrow = s_q + k*128;
    const float* wrow = Wk + f*128;
    for (int fb = 0; fb < 128; fb += 8){
      float v[8];
      #pragma unroll
      for (int u = 0; u < 8; u++) v[u] = __ldg(wrow + fb + u);
      #pragma unroll
      for (int u = 0; u < 8; u++) qp = fmaf(qrow[fb+u], v[u], qp);
    }
    s_qp[idx] = qp;
    g_c1[b*2048 + idx] = liw[f] * qp;
  }
  __syncthreads();
  if (t < NSLOT){
    float a2 = 0.f, a3 = 0.f;
    for (int f = 0; f < 256; f++){
      a2 = fmaf(liw[f], s_qp[t*256 + f], a2);
      a3 = fmaf(lib[f], s_qp[t*256 + f], a3);
    }
    g_c2[b*NSLOT + t] = a2;
    g_c3[b*NSLOT + t] = a3;
  }
}

// ---------------- launch ----------------
extern "C" void kernel_launch(void* const* d_in, const int* in_sizes, int n_in,
                              void* d_out, int out_size){
  const float* inputs   = (const float*)d_in[0];
  const float* slotinit = (const float*)d_in[1];
  const float* Wq       = (const float*)d_in[2];
  const float* Wk       = (const float*)d_in[3];
  const float* Wv       = (const float*)d_in[4];
  const float* gru_wi   = (const float*)d_in[5];
  const float* gru_wh   = (const float*)d_in[6];
  const float* gru_bi   = (const float*)d_in[7];
  const float* gru_bh   = (const float*)d_in[8];
  const float* ln_in_w  = (const float*)d_in[9];
  const float* ln_in_b  = (const float*)d_in[10];
  const float* ln_s_w   = (const float*)d_in[11];
  const float* ln_s_b   = (const float*)d_in[12];
  const float* ln_m_w   = (const float*)d_in[13];
  const float* ln_m_b   = (const float*)d_in[14];
  const float* mlp_w1   = (const float*)d_in[15];
  const float* mlp_b1   = (const float*)d_in[16];
  const float* mlp_w2   = (const float*)d_in[17];
  const float* mlp_b2   = (const float*)d_in[18];
  float* out = (float*)d_out;

  qprep0<<<NB, 384>>>(slotinit, out, Wq, Wk, ln_s_w, ln_s_b, ln_in_w, ln_in_b); // 1
  stats_k<<<(NB*NN)/8, 256>>>(inputs);                                          // 2
  dummy_k<<<1, 32>>>();                                                         // 3

  for (int it = 0; it < 3; it++){
    attn_scan<<<dim3(NB, NCH), 128>>>(inputs);   // 4th launch on it=0 (ncu)
    tail_bk<<<dim3(NB, NSLOT), 256>>>(out, gru_wi, gru_wh, gru_bi, gru_bh,
                           ln_m_w, ln_m_b, mlp_w1, mlp_b1, mlp_w2, mlp_b2,
                           Wq, Wk, Wv, ln_s_w, ln_s_b, ln_in_w, ln_in_b,
                           (it < 2) ? 1 : 0);
  }
}